// round 12
// baseline (speedup 1.0000x reference)
#include <cuda_runtime.h>
#include <cuda_bf16.h>
#include <cuda_fp16.h>
#include <cstdint>

// Problem constants (fixed by the dataset)
#define NN   50000
#define NPAD 50048        // 391 * 128
#define EE   800000
#define FIN  3
#define HH   256
#define GG   64
#define OUTD 24

// ---------------- scratch (device globals; no allocation allowed) -----------
__device__ float g_hf[NN * HH];           // final-layer fp32 activations (range > fp16 max!)
__device__ __half g_yh[(size_t)NN * HH];  // h @ w_rel, fp16 (gather payload)
__device__ __half g_zh[(size_t)NN * HH];  // h @ w_root + b, fp16
__device__ float g_agg3[NN * FIN];
__device__ float g_pooled[GG * HH];
__device__ int   g_deg[NN + 1];
__device__ int   g_rowptr[NN + 1];
__device__ int   g_cursor[NN + 1];
__device__ int   g_csr[EE];
__device__ int   g_bsums[256];
// tensor-core path scratch (single fp16, no hi/lo split)
__device__ __half g_Ah[(size_t)NPAD * 256];            // activations, fp16 (pad rows: zero)
__device__ __half g_Bh[(size_t)6 * 512 * 256];         // per layer: [n(512)][k(256)] fp16, K-major

// ---------------- PTX helpers (family-safe only: mma.sync / ldmatrix / cp.async)
__device__ __forceinline__ uint32_t smem_u32(const void* p) {
    uint32_t a;
    asm("{ .reg .u64 t; cvta.to.shared.u64 t, %1; cvt.u32.u64 %0, t; }" : "=r"(a) : "l"(p));
    return a;
}
__device__ __forceinline__ void cp16(uint32_t saddr, const void* gptr) {
    asm volatile("cp.async.cg.shared.global [%0], [%1], 16;" :: "r"(saddr), "l"(gptr) : "memory");
}
__device__ __forceinline__ void cp_commit() {
    asm volatile("cp.async.commit_group;" ::: "memory");
}
__device__ __forceinline__ void cp_wait1() {
    asm volatile("cp.async.wait_group 1;" ::: "memory");
}
__device__ __forceinline__ void cp_wait0() {
    asm volatile("cp.async.wait_group 0;" ::: "memory");
}
__device__ __forceinline__ void ldmx4(uint32_t* r, uint32_t addr) {
    asm volatile("ldmatrix.sync.aligned.m8n8.x4.shared.b16 {%0,%1,%2,%3}, [%4];"
                 : "=r"(r[0]), "=r"(r[1]), "=r"(r[2]), "=r"(r[3]) : "r"(addr));
}
__device__ __forceinline__ void mma16816(float* c, const uint32_t* a, uint32_t b0, uint32_t b1) {
    asm volatile(
        "mma.sync.aligned.m16n8k16.row.col.f32.f16.f16.f32 "
        "{%0,%1,%2,%3}, {%4,%5,%6,%7}, {%8,%9}, {%0,%1,%2,%3};"
        : "+f"(c[0]), "+f"(c[1]), "+f"(c[2]), "+f"(c[3])
        : "r"(a[0]), "r"(a[1]), "r"(a[2]), "r"(a[3]), "r"(b0), "r"(b1));
}
// 128B-atom XOR swizzle (bank-conflict-free STS/ldmatrix)
__device__ __forceinline__ uint32_t SWZ(uint32_t x) { return x ^ ((x >> 3) & 0x70); }

// ---------------- CSR construction ------------------------------------------
__global__ void zero2_kernel(int* a, int* b, int n) {
    int i = blockIdx.x * blockDim.x + threadIdx.x;
    if (i < n) { a[i] = 0; b[i] = 0; }
}

__global__ void count_deg_kernel(const int* __restrict__ dst, int* __restrict__ deg, int e) {
    int i = blockIdx.x * blockDim.x + threadIdx.x;
    if (i < e) atomicAdd(&deg[dst[i]], 1);
}

// ---- parallel exclusive scan over NN elems: 3 phases, 256-elem blocks ----
#define SCAN_BLOCKS ((NN + 255) / 256)   // 196

__global__ void scan_pass1(const int* __restrict__ deg, int* __restrict__ bsums, int n) {
    int i = blockIdx.x * 256 + threadIdx.x;
    int v = (i < n) ? deg[i] : 0;
    #pragma unroll
    for (int o = 16; o > 0; o >>= 1) v += __shfl_down_sync(0xFFFFFFFF, v, o);
    __shared__ int ws[8];
    int wid = threadIdx.x >> 5, lane = threadIdx.x & 31;
    if (lane == 0) ws[wid] = v;
    __syncthreads();
    if (threadIdx.x == 0) {
        int s = 0;
        #pragma unroll
        for (int w = 0; w < 8; w++) s += ws[w];
        bsums[blockIdx.x] = s;
    }
}

__global__ void scan_pass2(int* __restrict__ bsums, int nb) {
    __shared__ int sh[256];
    int tid = threadIdx.x;
    int v = (tid < nb) ? bsums[tid] : 0;
    sh[tid] = v;
    __syncthreads();
    #pragma unroll
    for (int off = 1; off < 256; off <<= 1) {
        int t = (tid >= off) ? sh[tid - off] : 0;
        __syncthreads();
        sh[tid] += t;
        __syncthreads();
    }
    if (tid < nb) bsums[tid] = sh[tid] - v;   // exclusive
}

__global__ void scan_pass3(const int* __restrict__ deg, const int* __restrict__ bsums,
                           int* __restrict__ rowptr, int n) {
    __shared__ int sh[256];
    int i = blockIdx.x * 256 + threadIdx.x;
    int tid = threadIdx.x;
    int v = (i < n) ? deg[i] : 0;
    sh[tid] = v;
    __syncthreads();
    #pragma unroll
    for (int off = 1; off < 256; off <<= 1) {
        int t = (tid >= off) ? sh[tid - off] : 0;
        __syncthreads();
        sh[tid] += t;
        __syncthreads();
    }
    int incl = sh[tid];
    int base = bsums[blockIdx.x];
    if (i < n)  rowptr[i] = base + incl - v;
    if (i == n - 1) rowptr[n] = base + incl;
}

__global__ void fill_csr_kernel(const int* __restrict__ src, const int* __restrict__ dst,
                                const int* __restrict__ rowptr, int* __restrict__ cursor,
                                int* __restrict__ csr, int e) {
    int i = blockIdx.x * blockDim.x + threadIdx.x;
    if (i < e) {
        int d = dst[i];
        int pos = atomicAdd(&cursor[d], 1);
        csr[rowptr[d] + pos] = src[i];
    }
}

// ---------------- layer 1 (F_IN=3 -> H), writes Ah fp16 directly -------------
__global__ void aggx_kernel(const float* __restrict__ x,
                            const int* __restrict__ rowptr, const int* __restrict__ csr,
                            float* __restrict__ agg3, int n) {
    int i = blockIdx.x * blockDim.x + threadIdx.x;
    if (i >= n) return;
    float a0 = 0.f, a1 = 0.f, a2 = 0.f;
    int beg = rowptr[i], end = rowptr[i + 1];
    for (int e = beg; e < end; e++) {
        int s = csr[e];
        a0 += x[s * 3 + 0];
        a1 += x[s * 3 + 1];
        a2 += x[s * 3 + 2];
    }
    agg3[i * 3 + 0] = a0;
    agg3[i * 3 + 1] = a1;
    agg3[i * 3 + 2] = a2;
}

__global__ void layer1_kernel(const float* __restrict__ x, const float* __restrict__ agg3,
                              const float* __restrict__ wr, const float* __restrict__ wro,
                              const float* __restrict__ b1, __half* __restrict__ Ah) {
    int n = blockIdx.x;
    int j = threadIdx.x;  // 256
    __shared__ float sx[3], sa[3];
    if (j < 3) { sx[j] = x[n * 3 + j]; sa[j] = agg3[n * 3 + j]; }
    __syncthreads();
    float v = b1[j];
    #pragma unroll
    for (int f = 0; f < 3; f++)
        v += sa[f] * wr[f * HH + j] + sx[f] * wro[f * HH + j];
    v = fmaxf(v, 0.f);
    Ah[(size_t)n * 256 + j] = __float2half_rn(v);
}

// ---------------- weight prep: fp32 [K,N] -> fp16 [N][256] K-major -----------
__global__ void prep_weights_kernel(const float* __restrict__ w_rel, const float* __restrict__ w_root,
                                    __half* __restrict__ Bh) {
    int idx = blockIdx.x * blockDim.x + threadIdx.x;
    if (idx >= 6 * 512 * 256) return;
    int k = idx & 255;
    int n = (idx >> 8) & 511;
    int L = idx >> 17;
    float w = (n < 256) ? w_rel[(size_t)L * 65536 + k * 256 + n]
                        : w_root[(size_t)L * 65536 + k * 256 + (n - 256)];
    Bh[(size_t)L * 512 * 256 + (size_t)n * 256 + k] = __float2half_rn(w);
}

// ---------------- mma.sync GEMM ----------------------------------------------
// C[128,128] per CTA; C = A[M,256] x B^T (fp16 in, fp32 acc, fp16 out).
// grid (391, 4): blockIdx.y 0,1 -> Yh cols 0/128; 2,3 -> Zh cols 0/128 (+bias).
// 8 warps: wm = wid>>1 (4 x 32 rows), wn = wid&1 (2 x 64 cols).
// K = 256 = 4 chunks of 64; SMEM: 2 stages x (A 16KB + B 16KB) = 64KB.
#define GEMM_SMEM_TOTAL (2 * 32768)
#define K_CHUNKS 4

__device__ __forceinline__ void load_chunk_cp(uint32_t sdst, int c, int bm, int nb,
                                              const __half* __restrict__ Ah,
                                              const __half* __restrict__ Bh) {
    int tid = threadIdx.x;
    #pragma unroll
    for (int i = 0; i < 4; i++) {                  // A: 128 rows x 128B
        int v = tid + i * 256;
        int r = v >> 3, kc = v & 7;
        const void* g = Ah + (size_t)(bm + r) * 256 + c * 64 + kc * 8;
        cp16(sdst + SWZ(r * 128 + kc * 16), g);
    }
    uint32_t bdst = sdst + 16384;
    #pragma unroll
    for (int i = 0; i < 4; i++) {                  // B: 128 n-rows x 128B
        int v = tid + i * 256;
        int r = v >> 3, kc = v & 7;
        const void* g = Bh + (size_t)(nb * 128 + r) * 256 + c * 64 + kc * 8;
        cp16(bdst + SWZ(r * 128 + kc * 16), g);
    }
}

__global__ __launch_bounds__(256)
void gemm_tc_kernel(const __half* __restrict__ Ah, const __half* __restrict__ Bh,
                    const float* __restrict__ bias, __half* __restrict__ Yh, __half* __restrict__ Zh) {
    extern __shared__ char smem[];
    uint32_t sb = smem_u32(smem);
    int tid = threadIdx.x, wid = tid >> 5, lane = tid & 31;
    int bm = blockIdx.x * 128;
    int nb = blockIdx.y;
    int wm = wid >> 1, wn = wid & 1;

    float acc[2][8][4];
    #pragma unroll
    for (int t = 0; t < 2; t++)
        #pragma unroll
        for (int u = 0; u < 8; u++)
            #pragma unroll
            for (int e = 0; e < 4; e++) acc[t][u][e] = 0.f;

    load_chunk_cp(sb, 0, bm, nb, Ah, Bh);
    cp_commit();

    for (int ch = 0; ch < K_CHUNKS; ch++) {
        int st = ch & 1;
        if (ch + 1 < K_CHUNKS) {
            load_chunk_cp(sb + (st ^ 1) * 32768, ch + 1, bm, nb, Ah, Bh);
            cp_commit();
            cp_wait1();
        } else {
            cp_wait0();
        }
        __syncthreads();

        uint32_t As = sb + st * 32768;
        uint32_t Bs = As + 16384;
        #pragma unroll
        for (int s = 0; s < 4; s++) {
            uint32_t a[2][4], bfrag[4][4];
            #pragma unroll
            for (int t = 0; t < 2; t++) {
                int m_local = wm * 32 + t * 16 + ((lane >> 3) & 1) * 8 + (lane & 7);
                int kseg = s * 2 + (lane >> 4);
                ldmx4(a[t], As + SWZ(m_local * 128 + kseg * 16));
            }
            #pragma unroll
            for (int j = 0; j < 4; j++) {
                int n_local = wn * 64 + (2 * j + (lane >> 4)) * 8 + (lane & 7);
                int kseg = s * 2 + ((lane >> 3) & 1);
                ldmx4(bfrag[j], Bs + SWZ(n_local * 128 + kseg * 16));
            }
            #pragma unroll
            for (int t = 0; t < 2; t++)
                #pragma unroll
                for (int u = 0; u < 8; u++)
                    mma16816(acc[t][u], a[t], bfrag[u >> 1][(u & 1) * 2],
                             bfrag[u >> 1][(u & 1) * 2 + 1]);
        }
        __syncthreads();
    }

    // epilogue (fp16 outputs)
    bool isY = (nb < 2);
    __half* C = isY ? Yh : Zh;
    int colbase = (nb & 1) * 128 + wn * 64;
    #pragma unroll
    for (int t = 0; t < 2; t++) {
        int m0 = bm + wm * 32 + t * 16 + (lane >> 2);
        #pragma unroll
        for (int u = 0; u < 8; u++) {
            int col = colbase + u * 8 + (lane & 3) * 2;
            float v0 = acc[t][u][0], v1 = acc[t][u][1];
            float v2 = acc[t][u][2], v3 = acc[t][u][3];
            if (!isY) {
                float2 bb = *(const float2*)(bias + col);
                v0 += bb.x; v1 += bb.y; v2 += bb.x; v3 += bb.y;
            }
            if (m0 < NN)     *(__half2*)(C + (size_t)m0 * 256 + col)       = __floats2half2_rn(v0, v1);
            if (m0 + 8 < NN) *(__half2*)(C + (size_t)(m0 + 8) * 256 + col) = __floats2half2_rn(v2, v3);
        }
    }
}

// ------ aggregation: out = relu(gather_sum(Yh) + Zh), 2-way unroll -----------
// Ahout != nullptr: fp16 out (layers 1..5). F32out != nullptr: fp32 out (last layer;
// final activations exceed fp16 range — see R11 post-mortem).
__global__ void aggregate_relu_kernel(const __half* __restrict__ Yh, const __half* __restrict__ Zh,
                                      const int* __restrict__ rowptr, const int* __restrict__ csr,
                                      __half* __restrict__ Ahout, float* __restrict__ F32out,
                                      int n) {
    int warp = (blockIdx.x * blockDim.x + threadIdx.x) >> 5;
    int lane = threadIdx.x & 31;
    if (warp >= n) return;
    int beg = rowptr[warp], end = rowptr[warp + 1];
    size_t off = (size_t)warp * HH + lane * 8;

    float4 acc0, acc1;
    {
        uint4 q = *(const uint4*)(Zh + off);
        float2 f0 = __half22float2(*(__half2*)&q.x);
        float2 f1 = __half22float2(*(__half2*)&q.y);
        float2 f2 = __half22float2(*(__half2*)&q.z);
        float2 f3 = __half22float2(*(__half2*)&q.w);
        acc0 = make_float4(f0.x, f0.y, f1.x, f1.y);
        acc1 = make_float4(f2.x, f2.y, f3.x, f3.y);
    }
    int e = beg;
    for (; e + 1 < end; e += 2) {
        int s0 = csr[e], s1 = csr[e + 1];
        uint4 p = *(const uint4*)(Yh + (size_t)s0 * HH + lane * 8);
        uint4 q = *(const uint4*)(Yh + (size_t)s1 * HH + lane * 8);
        float2 p0 = __half22float2(*(__half2*)&p.x);
        float2 p1 = __half22float2(*(__half2*)&p.y);
        float2 p2 = __half22float2(*(__half2*)&p.z);
        float2 p3 = __half22float2(*(__half2*)&p.w);
        float2 q0 = __half22float2(*(__half2*)&q.x);
        float2 q1 = __half22float2(*(__half2*)&q.y);
        float2 q2 = __half22float2(*(__half2*)&q.z);
        float2 q3 = __half22float2(*(__half2*)&q.w);
        acc0.x += p0.x + q0.x; acc0.y += p0.y + q0.y;
        acc0.z += p1.x + q1.x; acc0.w += p1.y + q1.y;
        acc1.x += p2.x + q2.x; acc1.y += p2.y + q2.y;
        acc1.z += p3.x + q3.x; acc1.w += p3.y + q3.y;
    }
    if (e < end) {
        int s0 = csr[e];
        uint4 p = *(const uint4*)(Yh + (size_t)s0 * HH + lane * 8);
        float2 p0 = __half22float2(*(__half2*)&p.x);
        float2 p1 = __half22float2(*(__half2*)&p.y);
        float2 p2 = __half22float2(*(__half2*)&p.z);
        float2 p3 = __half22float2(*(__half2*)&p.w);
        acc0.x += p0.x; acc0.y += p0.y; acc0.z += p1.x; acc0.w += p1.y;
        acc1.x += p2.x; acc1.y += p2.y; acc1.z += p3.x; acc1.w += p3.y;
    }
    acc0.x = fmaxf(acc0.x, 0.f); acc0.y = fmaxf(acc0.y, 0.f);
    acc0.z = fmaxf(acc0.z, 0.f); acc0.w = fmaxf(acc0.w, 0.f);
    acc1.x = fmaxf(acc1.x, 0.f); acc1.y = fmaxf(acc1.y, 0.f);
    acc1.z = fmaxf(acc1.z, 0.f); acc1.w = fmaxf(acc1.w, 0.f);

    if (F32out) {
        *(float4*)(F32out + off)     = acc0;
        *(float4*)(F32out + off + 4) = acc1;
    }
    if (Ahout) {
        uint4 o;
        *(__half2*)&o.x = __floats2half2_rn(acc0.x, acc0.y);
        *(__half2*)&o.y = __floats2half2_rn(acc0.z, acc0.w);
        *(__half2*)&o.z = __floats2half2_rn(acc1.x, acc1.y);
        *(__half2*)&o.w = __floats2half2_rn(acc1.z, acc1.w);
        *(uint4*)(Ahout + (size_t)warp * 256 + lane * 8) = o;
    }
}

// ---------------- mean pool over sorted batch ids (fp32 input) ---------------
__device__ __forceinline__ int lower_bound_dev(const int* a, int n, int key) {
    int lo = 0, hi = n;
    while (lo < hi) {
        int mid = (lo + hi) >> 1;
        if (a[mid] < key) lo = mid + 1; else hi = mid;
    }
    return lo;
}

__global__ void pool_kernel(const float* __restrict__ H, const int* __restrict__ batch,
                            float* __restrict__ pooled, int n) {
    int g = blockIdx.x;
    int j = threadIdx.x;  // 256
    __shared__ int s_lo, s_hi;
    if (j == 0) {
        s_lo = lower_bound_dev(batch, n, g);
        s_hi = lower_bound_dev(batch, n, g + 1);
    }
    __syncthreads();
    int lo = s_lo, hi = s_hi;
    float acc = 0.f;
    for (int nd = lo; nd < hi; nd++) acc += H[(size_t)nd * HH + j];
    int cnt = hi - lo;
    pooled[g * HH + j] = acc / (float)max(cnt, 1);
}

// ---------------- output head ------------------------------------------------
__global__ void head_kernel(const float* __restrict__ pooled, const float* __restrict__ w_out,
                            const float* __restrict__ b_out, float* __restrict__ out) {
    int g = blockIdx.x;
    int j = threadIdx.x;  // 32, guard 24
    if (j >= OUTD) return;
    float acc = b_out[j];
    #pragma unroll 8
    for (int k = 0; k < HH; k++)
        acc += pooled[g * HH + k] * w_out[k * OUTD + j];
    out[g * OUTD + j] = acc;
}

// ---------------- launch -----------------------------------------------------
extern "C" void kernel_launch(void* const* d_in, const int* in_sizes, int n_in,
                              void* d_out, int out_size) {
    const float* x       = (const float*)d_in[0];
    const int*   ei      = (const int*)d_in[1];
    const int*   batch   = (const int*)d_in[2];
    const float* w_rel1  = (const float*)d_in[3];
    const float* w_root1 = (const float*)d_in[4];
    const float* b1      = (const float*)d_in[5];
    const float* w_rel   = (const float*)d_in[6];   // 6 x 256 x 256
    const float* w_root  = (const float*)d_in[7];
    const float* b       = (const float*)d_in[8];   // 6 x 256
    const float* w_out   = (const float*)d_in[9];
    const float* b_out   = (const float*)d_in[10];
    float* out = (float*)d_out;

    const int* src = ei;        // edge_index[0]
    const int* dst = ei + EE;   // edge_index[1]

    float *hf, *agg3, *pooled;
    __half *yh, *zh, *Ah, *Bh;
    int *deg, *rowptr, *cursor, *csr, *bsums;
    cudaGetSymbolAddress((void**)&hf, g_hf);
    cudaGetSymbolAddress((void**)&yh, g_yh);
    cudaGetSymbolAddress((void**)&zh, g_zh);
    cudaGetSymbolAddress((void**)&agg3, g_agg3);
    cudaGetSymbolAddress((void**)&pooled, g_pooled);
    cudaGetSymbolAddress((void**)&deg, g_deg);
    cudaGetSymbolAddress((void**)&rowptr, g_rowptr);
    cudaGetSymbolAddress((void**)&cursor, g_cursor);
    cudaGetSymbolAddress((void**)&csr, g_csr);
    cudaGetSymbolAddress((void**)&bsums, g_bsums);
    cudaGetSymbolAddress((void**)&Ah, g_Ah);
    cudaGetSymbolAddress((void**)&Bh, g_Bh);

    cudaFuncSetAttribute(gemm_tc_kernel, cudaFuncAttributeMaxDynamicSharedMemorySize, GEMM_SMEM_TOTAL);

    // ---- build CSR (once per launch) ----
    zero2_kernel<<<(NN + 255) / 256, 256>>>(deg, cursor, NN);
    count_deg_kernel<<<(EE + 255) / 256, 256>>>(dst, deg, EE);
    scan_pass1<<<SCAN_BLOCKS, 256>>>(deg, bsums, NN);
    scan_pass2<<<1, 256>>>(bsums, SCAN_BLOCKS);
    scan_pass3<<<SCAN_BLOCKS, 256>>>(deg, bsums, rowptr, NN);
    fill_csr_kernel<<<(EE + 255) / 256, 256>>>(src, dst, rowptr, cursor, csr, EE);

    // ---- weight prep (fp16, K-major) ----
    prep_weights_kernel<<<(6 * 512 * 256 + 255) / 256, 256>>>(w_rel, w_root, Bh);

    // ---- layer 1 (3 -> 256), fp32 -> Ah fp16 directly ----
    aggx_kernel<<<(NN + 255) / 256, 256>>>(x, rowptr, csr, agg3, NN);
    layer1_kernel<<<NN, 256>>>(x, agg3, w_rel1, w_root1, b1, Ah);

    // ---- layers 2..7 (256 -> 256), tensor cores via mma.sync fp16 ----
    dim3 ggrid(NPAD / 128, 4);
    for (int i = 0; i < 6; i++) {
        gemm_tc_kernel<<<ggrid, 256, GEMM_SMEM_TOTAL>>>(Ah, Bh + (size_t)i * 512 * 256,
                                                        b + i * HH, yh, zh);
        bool last = (i == 5);
        aggregate_relu_kernel<<<(NN * 32 + 255) / 256, 256>>>(
            yh, zh, rowptr, csr,
            last ? (__half*)nullptr : Ah,
            last ? hf : (float*)nullptr, NN);
    }

    // ---- pool + head (pool reads fp32 hf — final layer exceeds fp16 range) ----
    pool_kernel<<<GG, 256>>>(hf, batch, pooled, NN);
    head_kernel<<<GG, 32>>>(pooled, w_out, b_out, out);
}

// round 13
// speedup vs baseline: 1.0104x; 1.0104x over previous
#include <cuda_runtime.h>
#include <cuda_bf16.h>
#include <cuda_fp16.h>
#include <cstdint>

// Problem constants (fixed by the dataset)
#define NN   50000
#define NPAD 50048        // 391 * 128
#define EE   800000
#define FIN  3
#define HH   256
#define GG   64
#define OUTD 24

// ---------------- scratch (device globals; no allocation allowed) -----------
__device__ float g_hf[NN * HH];           // final-layer fp32 activations (range > fp16 max!)
__device__ __half g_yh[(size_t)NN * HH];  // h @ w_rel, fp16 (gather payload)
__device__ __half g_zh[(size_t)NN * HH];  // h @ w_root + b, fp16
__device__ float g_agg3[NN * FIN];
__device__ float g_pooled[GG * HH];
__device__ int   g_deg[NN + 1];
__device__ int   g_rowptr[NN + 1];
__device__ int   g_cursor[NN + 1];
__device__ int   g_csr[EE];
__device__ int   g_bsums[256];
// tensor-core path scratch (single fp16, no hi/lo split)
__device__ __half g_Ah[(size_t)NPAD * 256];            // activations, fp16 (pad rows: zero)
__device__ __half g_Bh[(size_t)6 * 512 * 256];         // per layer: [n(512)][k(256)] fp16, K-major

// ---------------- PTX helpers (family-safe only: mma.sync / ldmatrix / cp.async)
__device__ __forceinline__ uint32_t smem_u32(const void* p) {
    uint32_t a;
    asm("{ .reg .u64 t; cvta.to.shared.u64 t, %1; cvt.u32.u64 %0, t; }" : "=r"(a) : "l"(p));
    return a;
}
__device__ __forceinline__ void cp16(uint32_t saddr, const void* gptr) {
    asm volatile("cp.async.cg.shared.global [%0], [%1], 16;" :: "r"(saddr), "l"(gptr) : "memory");
}
__device__ __forceinline__ void cp_commit() {
    asm volatile("cp.async.commit_group;" ::: "memory");
}
__device__ __forceinline__ void cp_wait1() {
    asm volatile("cp.async.wait_group 1;" ::: "memory");
}
__device__ __forceinline__ void cp_wait0() {
    asm volatile("cp.async.wait_group 0;" ::: "memory");
}
__device__ __forceinline__ void ldmx4(uint32_t* r, uint32_t addr) {
    asm volatile("ldmatrix.sync.aligned.m8n8.x4.shared.b16 {%0,%1,%2,%3}, [%4];"
                 : "=r"(r[0]), "=r"(r[1]), "=r"(r[2]), "=r"(r[3]) : "r"(addr));
}
__device__ __forceinline__ void mma16816(float* c, const uint32_t* a, uint32_t b0, uint32_t b1) {
    asm volatile(
        "mma.sync.aligned.m16n8k16.row.col.f32.f16.f16.f32 "
        "{%0,%1,%2,%3}, {%4,%5,%6,%7}, {%8,%9}, {%0,%1,%2,%3};"
        : "+f"(c[0]), "+f"(c[1]), "+f"(c[2]), "+f"(c[3])
        : "r"(a[0]), "r"(a[1]), "r"(a[2]), "r"(a[3]), "r"(b0), "r"(b1));
}
// 128B-atom XOR swizzle (bank-conflict-free STS/ldmatrix)
__device__ __forceinline__ uint32_t SWZ(uint32_t x) { return x ^ ((x >> 3) & 0x70); }

// ---------------- CSR construction ------------------------------------------
__global__ void zero2_kernel(int* a, int* b, int n) {
    int i = blockIdx.x * blockDim.x + threadIdx.x;
    if (i < n) { a[i] = 0; b[i] = 0; }
}

__global__ void count_deg_kernel(const int* __restrict__ dst, int* __restrict__ deg, int e) {
    int i = blockIdx.x * blockDim.x + threadIdx.x;
    if (i < e) atomicAdd(&deg[dst[i]], 1);
}

// ---- parallel exclusive scan over NN elems: 3 phases, 256-elem blocks ----
#define SCAN_BLOCKS ((NN + 255) / 256)   // 196

__global__ void scan_pass1(const int* __restrict__ deg, int* __restrict__ bsums, int n) {
    int i = blockIdx.x * 256 + threadIdx.x;
    int v = (i < n) ? deg[i] : 0;
    #pragma unroll
    for (int o = 16; o > 0; o >>= 1) v += __shfl_down_sync(0xFFFFFFFF, v, o);
    __shared__ int ws[8];
    int wid = threadIdx.x >> 5, lane = threadIdx.x & 31;
    if (lane == 0) ws[wid] = v;
    __syncthreads();
    if (threadIdx.x == 0) {
        int s = 0;
        #pragma unroll
        for (int w = 0; w < 8; w++) s += ws[w];
        bsums[blockIdx.x] = s;
    }
}

__global__ void scan_pass2(int* __restrict__ bsums, int nb) {
    __shared__ int sh[256];
    int tid = threadIdx.x;
    int v = (tid < nb) ? bsums[tid] : 0;
    sh[tid] = v;
    __syncthreads();
    #pragma unroll
    for (int off = 1; off < 256; off <<= 1) {
        int t = (tid >= off) ? sh[tid - off] : 0;
        __syncthreads();
        sh[tid] += t;
        __syncthreads();
    }
    if (tid < nb) bsums[tid] = sh[tid] - v;   // exclusive
}

__global__ void scan_pass3(const int* __restrict__ deg, const int* __restrict__ bsums,
                           int* __restrict__ rowptr, int n) {
    __shared__ int sh[256];
    int i = blockIdx.x * 256 + threadIdx.x;
    int tid = threadIdx.x;
    int v = (i < n) ? deg[i] : 0;
    sh[tid] = v;
    __syncthreads();
    #pragma unroll
    for (int off = 1; off < 256; off <<= 1) {
        int t = (tid >= off) ? sh[tid - off] : 0;
        __syncthreads();
        sh[tid] += t;
        __syncthreads();
    }
    int incl = sh[tid];
    int base = bsums[blockIdx.x];
    if (i < n)  rowptr[i] = base + incl - v;
    if (i == n - 1) rowptr[n] = base + incl;
}

__global__ void fill_csr_kernel(const int* __restrict__ src, const int* __restrict__ dst,
                                const int* __restrict__ rowptr, int* __restrict__ cursor,
                                int* __restrict__ csr, int e) {
    int i = blockIdx.x * blockDim.x + threadIdx.x;
    if (i < e) {
        int d = dst[i];
        int pos = atomicAdd(&cursor[d], 1);
        csr[rowptr[d] + pos] = src[i];
    }
}

// ---------------- layer 1 (F_IN=3 -> H), writes Ah fp16 directly -------------
__global__ void aggx_kernel(const float* __restrict__ x,
                            const int* __restrict__ rowptr, const int* __restrict__ csr,
                            float* __restrict__ agg3, int n) {
    int i = blockIdx.x * blockDim.x + threadIdx.x;
    if (i >= n) return;
    float a0 = 0.f, a1 = 0.f, a2 = 0.f;
    int beg = rowptr[i], end = rowptr[i + 1];
    for (int e = beg; e < end; e++) {
        int s = csr[e];
        a0 += x[s * 3 + 0];
        a1 += x[s * 3 + 1];
        a2 += x[s * 3 + 2];
    }
    agg3[i * 3 + 0] = a0;
    agg3[i * 3 + 1] = a1;
    agg3[i * 3 + 2] = a2;
}

__global__ void layer1_kernel(const float* __restrict__ x, const float* __restrict__ agg3,
                              const float* __restrict__ wr, const float* __restrict__ wro,
                              const float* __restrict__ b1, __half* __restrict__ Ah) {
    int n = blockIdx.x;
    int j = threadIdx.x;  // 256
    __shared__ float sx[3], sa[3];
    if (j < 3) { sx[j] = x[n * 3 + j]; sa[j] = agg3[n * 3 + j]; }
    __syncthreads();
    float v = b1[j];
    #pragma unroll
    for (int f = 0; f < 3; f++)
        v += sa[f] * wr[f * HH + j] + sx[f] * wro[f * HH + j];
    v = fmaxf(v, 0.f);
    Ah[(size_t)n * 256 + j] = __float2half_rn(v);
}

// ---------------- weight prep: fp32 [K,N] -> fp16 [N][256] K-major -----------
__global__ void prep_weights_kernel(const float* __restrict__ w_rel, const float* __restrict__ w_root,
                                    __half* __restrict__ Bh) {
    int idx = blockIdx.x * blockDim.x + threadIdx.x;
    if (idx >= 6 * 512 * 256) return;
    int k = idx & 255;
    int n = (idx >> 8) & 511;
    int L = idx >> 17;
    float w = (n < 256) ? w_rel[(size_t)L * 65536 + k * 256 + n]
                        : w_root[(size_t)L * 65536 + k * 256 + (n - 256)];
    Bh[(size_t)L * 512 * 256 + (size_t)n * 256 + k] = __float2half_rn(w);
}

// ---------------- mma.sync GEMM ----------------------------------------------
// C[128,128] per CTA; C = A[M,256] x B^T (fp16 in, fp32 acc, fp16 out).
// grid (391, 4): blockIdx.y 0,1 -> Yh cols 0/128; 2,3 -> Zh cols 0/128 (+bias).
// 8 warps: wm = wid>>1 (4 x 32 rows), wn = wid&1 (2 x 64 cols).
// K = 256 = 4 chunks of 64; SMEM: 2 stages x (A 16KB + B 16KB) = 64KB.
#define GEMM_SMEM_TOTAL (2 * 32768)
#define K_CHUNKS 4

__device__ __forceinline__ void load_chunk_cp(uint32_t sdst, int c, int bm, int nb,
                                              const __half* __restrict__ Ah,
                                              const __half* __restrict__ Bh) {
    int tid = threadIdx.x;
    #pragma unroll
    for (int i = 0; i < 4; i++) {                  // A: 128 rows x 128B
        int v = tid + i * 256;
        int r = v >> 3, kc = v & 7;
        const void* g = Ah + (size_t)(bm + r) * 256 + c * 64 + kc * 8;
        cp16(sdst + SWZ(r * 128 + kc * 16), g);
    }
    uint32_t bdst = sdst + 16384;
    #pragma unroll
    for (int i = 0; i < 4; i++) {                  // B: 128 n-rows x 128B
        int v = tid + i * 256;
        int r = v >> 3, kc = v & 7;
        const void* g = Bh + (size_t)(nb * 128 + r) * 256 + c * 64 + kc * 8;
        cp16(bdst + SWZ(r * 128 + kc * 16), g);
    }
}

__global__ __launch_bounds__(256)
void gemm_tc_kernel(const __half* __restrict__ Ah, const __half* __restrict__ Bh,
                    const float* __restrict__ bias, __half* __restrict__ Yh, __half* __restrict__ Zh) {
    extern __shared__ char smem[];
    uint32_t sb = smem_u32(smem);
    int tid = threadIdx.x, wid = tid >> 5, lane = tid & 31;
    int bm = blockIdx.x * 128;
    int nb = blockIdx.y;
    int wm = wid >> 1, wn = wid & 1;

    float acc[2][8][4];
    #pragma unroll
    for (int t = 0; t < 2; t++)
        #pragma unroll
        for (int u = 0; u < 8; u++)
            #pragma unroll
            for (int e = 0; e < 4; e++) acc[t][u][e] = 0.f;

    load_chunk_cp(sb, 0, bm, nb, Ah, Bh);
    cp_commit();

    for (int ch = 0; ch < K_CHUNKS; ch++) {
        int st = ch & 1;
        if (ch + 1 < K_CHUNKS) {
            load_chunk_cp(sb + (st ^ 1) * 32768, ch + 1, bm, nb, Ah, Bh);
            cp_commit();
            cp_wait1();
        } else {
            cp_wait0();
        }
        __syncthreads();

        uint32_t As = sb + st * 32768;
        uint32_t Bs = As + 16384;
        #pragma unroll
        for (int s = 0; s < 4; s++) {
            uint32_t a[2][4], bfrag[4][4];
            #pragma unroll
            for (int t = 0; t < 2; t++) {
                int m_local = wm * 32 + t * 16 + ((lane >> 3) & 1) * 8 + (lane & 7);
                int kseg = s * 2 + (lane >> 4);
                ldmx4(a[t], As + SWZ(m_local * 128 + kseg * 16));
            }
            #pragma unroll
            for (int j = 0; j < 4; j++) {
                int n_local = wn * 64 + (2 * j + (lane >> 4)) * 8 + (lane & 7);
                int kseg = s * 2 + ((lane >> 3) & 1);
                ldmx4(bfrag[j], Bs + SWZ(n_local * 128 + kseg * 16));
            }
            #pragma unroll
            for (int t = 0; t < 2; t++)
                #pragma unroll
                for (int u = 0; u < 8; u++)
                    mma16816(acc[t][u], a[t], bfrag[u >> 1][(u & 1) * 2],
                             bfrag[u >> 1][(u & 1) * 2 + 1]);
        }
        __syncthreads();
    }

    // epilogue (fp16 outputs)
    bool isY = (nb < 2);
    __half* C = isY ? Yh : Zh;
    int colbase = (nb & 1) * 128 + wn * 64;
    #pragma unroll
    for (int t = 0; t < 2; t++) {
        int m0 = bm + wm * 32 + t * 16 + (lane >> 2);
        #pragma unroll
        for (int u = 0; u < 8; u++) {
            int col = colbase + u * 8 + (lane & 3) * 2;
            float v0 = acc[t][u][0], v1 = acc[t][u][1];
            float v2 = acc[t][u][2], v3 = acc[t][u][3];
            if (!isY) {
                float2 bb = *(const float2*)(bias + col);
                v0 += bb.x; v1 += bb.y; v2 += bb.x; v3 += bb.y;
            }
            if (m0 < NN)     *(__half2*)(C + (size_t)m0 * 256 + col)       = __floats2half2_rn(v0, v1);
            if (m0 + 8 < NN) *(__half2*)(C + (size_t)(m0 + 8) * 256 + col) = __floats2half2_rn(v2, v3);
        }
    }
}

// ------ aggregation: out = relu(gather_sum(Yh) + Zh) -------------------------
// csr indices prefetched warp-coalesced and broadcast via shfl (keeps the
// index load off the row-gather critical path). Simple single-row loop body
// (the R12 2-way unroll regressed; reverted).
// Ahout != nullptr: fp16 out (layers 1..5). F32out != nullptr: fp32 out (last
// layer; final activations exceed fp16 range — see R11 post-mortem).
__global__ void aggregate_relu_kernel(const __half* __restrict__ Yh, const __half* __restrict__ Zh,
                                      const int* __restrict__ rowptr, const int* __restrict__ csr,
                                      __half* __restrict__ Ahout, float* __restrict__ F32out,
                                      int n) {
    int warp = (blockIdx.x * blockDim.x + threadIdx.x) >> 5;
    int lane = threadIdx.x & 31;
    if (warp >= n) return;
    int beg = rowptr[warp], end = rowptr[warp + 1];
    size_t off = (size_t)warp * HH + lane * 8;

    float4 acc0, acc1;
    {
        uint4 q = *(const uint4*)(Zh + off);
        float2 f0 = __half22float2(*(__half2*)&q.x);
        float2 f1 = __half22float2(*(__half2*)&q.y);
        float2 f2 = __half22float2(*(__half2*)&q.z);
        float2 f3 = __half22float2(*(__half2*)&q.w);
        acc0 = make_float4(f0.x, f0.y, f1.x, f1.y);
        acc1 = make_float4(f2.x, f2.y, f3.x, f3.y);
    }

    for (int base = beg; base < end; base += 32) {
        int m = end - base;
        if (m > 32) m = 32;
        int idx = 0;
        if (base + lane < end) idx = csr[base + lane];   // coalesced: 32 indices in 1 xact
        #pragma unroll 4
        for (int j = 0; j < m; j++) {
            int s0 = __shfl_sync(0xFFFFFFFF, idx, j);
            uint4 p = *(const uint4*)(Yh + (size_t)s0 * HH + lane * 8);
            float2 p0 = __half22float2(*(__half2*)&p.x);
            float2 p1 = __half22float2(*(__half2*)&p.y);
            float2 p2 = __half22float2(*(__half2*)&p.z);
            float2 p3 = __half22float2(*(__half2*)&p.w);
            acc0.x += p0.x; acc0.y += p0.y; acc0.z += p1.x; acc0.w += p1.y;
            acc1.x += p2.x; acc1.y += p2.y; acc1.z += p3.x; acc1.w += p3.y;
        }
    }

    acc0.x = fmaxf(acc0.x, 0.f); acc0.y = fmaxf(acc0.y, 0.f);
    acc0.z = fmaxf(acc0.z, 0.f); acc0.w = fmaxf(acc0.w, 0.f);
    acc1.x = fmaxf(acc1.x, 0.f); acc1.y = fmaxf(acc1.y, 0.f);
    acc1.z = fmaxf(acc1.z, 0.f); acc1.w = fmaxf(acc1.w, 0.f);

    if (F32out) {
        *(float4*)(F32out + off)     = acc0;
        *(float4*)(F32out + off + 4) = acc1;
    }
    if (Ahout) {
        uint4 o;
        *(__half2*)&o.x = __floats2half2_rn(acc0.x, acc0.y);
        *(__half2*)&o.y = __floats2half2_rn(acc0.z, acc0.w);
        *(__half2*)&o.z = __floats2half2_rn(acc1.x, acc1.y);
        *(__half2*)&o.w = __floats2half2_rn(acc1.z, acc1.w);
        *(uint4*)(Ahout + off) = o;
    }
}

// ---------------- mean pool over sorted batch ids (fp32 input) ---------------
__device__ __forceinline__ int lower_bound_dev(const int* a, int n, int key) {
    int lo = 0, hi = n;
    while (lo < hi) {
        int mid = (lo + hi) >> 1;
        if (a[mid] < key) lo = mid + 1; else hi = mid;
    }
    return lo;
}

__global__ void pool_kernel(const float* __restrict__ H, const int* __restrict__ batch,
                            float* __restrict__ pooled, int n) {
    int g = blockIdx.x;
    int j = threadIdx.x;  // 256
    __shared__ int s_lo, s_hi;
    if (j == 0) {
        s_lo = lower_bound_dev(batch, n, g);
        s_hi = lower_bound_dev(batch, n, g + 1);
    }
    __syncthreads();
    int lo = s_lo, hi = s_hi;
    float acc = 0.f;
    for (int nd = lo; nd < hi; nd++) acc += H[(size_t)nd * HH + j];
    int cnt = hi - lo;
    pooled[g * HH + j] = acc / (float)max(cnt, 1);
}

// ---------------- output head ------------------------------------------------
__global__ void head_kernel(const float* __restrict__ pooled, const float* __restrict__ w_out,
                            const float* __restrict__ b_out, float* __restrict__ out) {
    int g = blockIdx.x;
    int j = threadIdx.x;  // 32, guard 24
    if (j >= OUTD) return;
    float acc = b_out[j];
    #pragma unroll 8
    for (int k = 0; k < HH; k++)
        acc += pooled[g * HH + k] * w_out[k * OUTD + j];
    out[g * OUTD + j] = acc;
}

// ---------------- launch -----------------------------------------------------
extern "C" void kernel_launch(void* const* d_in, const int* in_sizes, int n_in,
                              void* d_out, int out_size) {
    const float* x       = (const float*)d_in[0];
    const int*   ei      = (const int*)d_in[1];
    const int*   batch   = (const int*)d_in[2];
    const float* w_rel1  = (const float*)d_in[3];
    const float* w_root1 = (const float*)d_in[4];
    const float* b1      = (const float*)d_in[5];
    const float* w_rel   = (const float*)d_in[6];   // 6 x 256 x 256
    const float* w_root  = (const float*)d_in[7];
    const float* b       = (const float*)d_in[8];   // 6 x 256
    const float* w_out   = (const float*)d_in[9];
    const float* b_out   = (const float*)d_in[10];
    float* out = (float*)d_out;

    const int* src = ei;        // edge_index[0]
    const int* dst = ei + EE;   // edge_index[1]

    float *hf, *agg3, *pooled;
    __half *yh, *zh, *Ah, *Bh;
    int *deg, *rowptr, *cursor, *csr, *bsums;
    cudaGetSymbolAddress((void**)&hf, g_hf);
    cudaGetSymbolAddress((void**)&yh, g_yh);
    cudaGetSymbolAddress((void**)&zh, g_zh);
    cudaGetSymbolAddress((void**)&agg3, g_agg3);
    cudaGetSymbolAddress((void**)&pooled, g_pooled);
    cudaGetSymbolAddress((void**)&deg, g_deg);
    cudaGetSymbolAddress((void**)&rowptr, g_rowptr);
    cudaGetSymbolAddress((void**)&cursor, g_cursor);
    cudaGetSymbolAddress((void**)&csr, g_csr);
    cudaGetSymbolAddress((void**)&bsums, g_bsums);
    cudaGetSymbolAddress((void**)&Ah, g_Ah);
    cudaGetSymbolAddress((void**)&Bh, g_Bh);

    cudaFuncSetAttribute(gemm_tc_kernel, cudaFuncAttributeMaxDynamicSharedMemorySize, GEMM_SMEM_TOTAL);

    // ---- build CSR (once per launch) ----
    zero2_kernel<<<(NN + 255) / 256, 256>>>(deg, cursor, NN);
    count_deg_kernel<<<(EE + 255) / 256, 256>>>(dst, deg, EE);
    scan_pass1<<<SCAN_BLOCKS, 256>>>(deg, bsums, NN);
    scan_pass2<<<1, 256>>>(bsums, SCAN_BLOCKS);
    scan_pass3<<<SCAN_BLOCKS, 256>>>(deg, bsums, rowptr, NN);
    fill_csr_kernel<<<(EE + 255) / 256, 256>>>(src, dst, rowptr, cursor, csr, EE);

    // ---- weight prep (fp16, K-major) ----
    prep_weights_kernel<<<(6 * 512 * 256 + 255) / 256, 256>>>(w_rel, w_root, Bh);

    // ---- layer 1 (3 -> 256), fp32 -> Ah fp16 directly ----
    aggx_kernel<<<(NN + 255) / 256, 256>>>(x, rowptr, csr, agg3, NN);
    layer1_kernel<<<NN, 256>>>(x, agg3, w_rel1, w_root1, b1, Ah);

    // ---- layers 2..7 (256 -> 256), tensor cores via mma.sync fp16 ----
    dim3 ggrid(NPAD / 128, 4);
    for (int i = 0; i < 6; i++) {
        gemm_tc_kernel<<<ggrid, 256, GEMM_SMEM_TOTAL>>>(Ah, Bh + (size_t)i * 512 * 256,
                                                        b + i * HH, yh, zh);
        bool last = (i == 5);
        aggregate_relu_kernel<<<(NN * 32 + 255) / 256, 256>>>(
            yh, zh, rowptr, csr,
            last ? (__half*)nullptr : Ah,
            last ? hf : (float*)nullptr, NN);
    }

    // ---- pool + head (pool reads fp32 hf — final layer exceeds fp16 range) ----
    pool_kernel<<<GG, 256>>>(hf, batch, pooled, NN);
    head_kernel<<<GG, 32>>>(pooled, w_out, b_out, out);
}

// round 14
// speedup vs baseline: 1.0390x; 1.0283x over previous
#include <cuda_runtime.h>
#include <cuda_bf16.h>
#include <cuda_fp16.h>
#include <cstdint>

// Problem constants (fixed by the dataset)
#define NN   50000
#define NPAD 50048        // 391 * 128
#define EE   800000
#define FIN  3
#define HH   256
#define GG   64
#define OUTD 24

// ---------------- scratch (device globals; no allocation allowed) -----------
__device__ float g_hf[NN * HH];           // final-layer fp32 activations (range > fp16 max!)
__device__ __half g_yh[(size_t)NN * HH];  // h @ w_rel, fp16 (gather payload)
__device__ __half g_zh[(size_t)NN * HH];  // h @ w_root + b, fp16
__device__ float g_agg3[NN * FIN];
__device__ int   g_deg[NN + 1];
__device__ int   g_rowptr[NN + 1];
__device__ int   g_cursor[NN + 1];
__device__ int   g_csr[EE];
__device__ int   g_bsums[256];
// tensor-core path scratch (single fp16, no hi/lo split)
__device__ __half g_Ah[(size_t)NPAD * 256];            // activations, fp16 (pad rows: zero)
__device__ __half g_Bh[(size_t)6 * 512 * 256];         // per layer: [n(512)][k(256)] fp16, K-major

// ---------------- PTX helpers (family-safe only: mma.sync / ldmatrix / cp.async)
__device__ __forceinline__ uint32_t smem_u32(const void* p) {
    uint32_t a;
    asm("{ .reg .u64 t; cvta.to.shared.u64 t, %1; cvt.u32.u64 %0, t; }" : "=r"(a) : "l"(p));
    return a;
}
__device__ __forceinline__ void cp16(uint32_t saddr, const void* gptr) {
    asm volatile("cp.async.cg.shared.global [%0], [%1], 16;" :: "r"(saddr), "l"(gptr) : "memory");
}
__device__ __forceinline__ void cp_commit() {
    asm volatile("cp.async.commit_group;" ::: "memory");
}
__device__ __forceinline__ void cp_wait1() {
    asm volatile("cp.async.wait_group 1;" ::: "memory");
}
__device__ __forceinline__ void cp_wait0() {
    asm volatile("cp.async.wait_group 0;" ::: "memory");
}
__device__ __forceinline__ void ldmx4(uint32_t* r, uint32_t addr) {
    asm volatile("ldmatrix.sync.aligned.m8n8.x4.shared.b16 {%0,%1,%2,%3}, [%4];"
                 : "=r"(r[0]), "=r"(r[1]), "=r"(r[2]), "=r"(r[3]) : "r"(addr));
}
__device__ __forceinline__ void mma16816(float* c, const uint32_t* a, uint32_t b0, uint32_t b1) {
    asm volatile(
        "mma.sync.aligned.m16n8k16.row.col.f32.f16.f16.f32 "
        "{%0,%1,%2,%3}, {%4,%5,%6,%7}, {%8,%9}, {%0,%1,%2,%3};"
        : "+f"(c[0]), "+f"(c[1]), "+f"(c[2]), "+f"(c[3])
        : "r"(a[0]), "r"(a[1]), "r"(a[2]), "r"(a[3]), "r"(b0), "r"(b1));
}
// 128B-atom XOR swizzle (bank-conflict-free STS/ldmatrix)
__device__ __forceinline__ uint32_t SWZ(uint32_t x) { return x ^ ((x >> 3) & 0x70); }

// ---------------- CSR construction ------------------------------------------
__global__ void zero2_kernel(int* a, int* b, int n) {
    int i = blockIdx.x * blockDim.x + threadIdx.x;
    if (i < n) { a[i] = 0; b[i] = 0; }
}

__global__ void count_deg_kernel(const int* __restrict__ dst, int* __restrict__ deg, int e) {
    int i = blockIdx.x * blockDim.x + threadIdx.x;
    if (i < e) atomicAdd(&deg[dst[i]], 1);
}

// ---- parallel exclusive scan over NN elems: 3 phases, 256-elem blocks ----
#define SCAN_BLOCKS ((NN + 255) / 256)   // 196

__global__ void scan_pass1(const int* __restrict__ deg, int* __restrict__ bsums, int n) {
    int i = blockIdx.x * 256 + threadIdx.x;
    int v = (i < n) ? deg[i] : 0;
    #pragma unroll
    for (int o = 16; o > 0; o >>= 1) v += __shfl_down_sync(0xFFFFFFFF, v, o);
    __shared__ int ws[8];
    int wid = threadIdx.x >> 5, lane = threadIdx.x & 31;
    if (lane == 0) ws[wid] = v;
    __syncthreads();
    if (threadIdx.x == 0) {
        int s = 0;
        #pragma unroll
        for (int w = 0; w < 8; w++) s += ws[w];
        bsums[blockIdx.x] = s;
    }
}

__global__ void scan_pass2(int* __restrict__ bsums, int nb) {
    __shared__ int sh[256];
    int tid = threadIdx.x;
    int v = (tid < nb) ? bsums[tid] : 0;
    sh[tid] = v;
    __syncthreads();
    #pragma unroll
    for (int off = 1; off < 256; off <<= 1) {
        int t = (tid >= off) ? sh[tid - off] : 0;
        __syncthreads();
        sh[tid] += t;
        __syncthreads();
    }
    if (tid < nb) bsums[tid] = sh[tid] - v;   // exclusive
}

__global__ void scan_pass3(const int* __restrict__ deg, const int* __restrict__ bsums,
                           int* __restrict__ rowptr, int n) {
    __shared__ int sh[256];
    int i = blockIdx.x * 256 + threadIdx.x;
    int tid = threadIdx.x;
    int v = (i < n) ? deg[i] : 0;
    sh[tid] = v;
    __syncthreads();
    #pragma unroll
    for (int off = 1; off < 256; off <<= 1) {
        int t = (tid >= off) ? sh[tid - off] : 0;
        __syncthreads();
        sh[tid] += t;
        __syncthreads();
    }
    int incl = sh[tid];
    int base = bsums[blockIdx.x];
    if (i < n)  rowptr[i] = base + incl - v;
    if (i == n - 1) rowptr[n] = base + incl;
}

__global__ void fill_csr_kernel(const int* __restrict__ src, const int* __restrict__ dst,
                                const int* __restrict__ rowptr, int* __restrict__ cursor,
                                int* __restrict__ csr, int e) {
    int i = blockIdx.x * blockDim.x + threadIdx.x;
    if (i < e) {
        int d = dst[i];
        int pos = atomicAdd(&cursor[d], 1);
        csr[rowptr[d] + pos] = src[i];
    }
}

// ---------------- layer 1 (F_IN=3 -> H), writes Ah fp16 directly -------------
__global__ void aggx_kernel(const float* __restrict__ x,
                            const int* __restrict__ rowptr, const int* __restrict__ csr,
                            float* __restrict__ agg3, int n) {
    int i = blockIdx.x * blockDim.x + threadIdx.x;
    if (i >= n) return;
    float a0 = 0.f, a1 = 0.f, a2 = 0.f;
    int beg = rowptr[i], end = rowptr[i + 1];
    for (int e = beg; e < end; e++) {
        int s = csr[e];
        a0 += x[s * 3 + 0];
        a1 += x[s * 3 + 1];
        a2 += x[s * 3 + 2];
    }
    agg3[i * 3 + 0] = a0;
    agg3[i * 3 + 1] = a1;
    agg3[i * 3 + 2] = a2;
}

__global__ void layer1_kernel(const float* __restrict__ x, const float* __restrict__ agg3,
                              const float* __restrict__ wr, const float* __restrict__ wro,
                              const float* __restrict__ b1, __half* __restrict__ Ah) {
    int n = blockIdx.x;
    int j = threadIdx.x;  // 256
    __shared__ float sx[3], sa[3];
    if (j < 3) { sx[j] = x[n * 3 + j]; sa[j] = agg3[n * 3 + j]; }
    __syncthreads();
    float v = b1[j];
    #pragma unroll
    for (int f = 0; f < 3; f++)
        v += sa[f] * wr[f * HH + j] + sx[f] * wro[f * HH + j];
    v = fmaxf(v, 0.f);
    Ah[(size_t)n * 256 + j] = __float2half_rn(v);
}

// ---------------- weight prep: fp32 [K,N] -> fp16 [N][256] K-major -----------
__global__ void prep_weights_kernel(const float* __restrict__ w_rel, const float* __restrict__ w_root,
                                    __half* __restrict__ Bh) {
    int idx = blockIdx.x * blockDim.x + threadIdx.x;
    if (idx >= 6 * 512 * 256) return;
    int k = idx & 255;
    int n = (idx >> 8) & 511;
    int L = idx >> 17;
    float w = (n < 256) ? w_rel[(size_t)L * 65536 + k * 256 + n]
                        : w_root[(size_t)L * 65536 + k * 256 + (n - 256)];
    Bh[(size_t)L * 512 * 256 + (size_t)n * 256 + k] = __float2half_rn(w);
}

// ---------------- mma.sync GEMM ----------------------------------------------
// C[128,128] per CTA; C = A[M,256] x B^T (fp16 in, fp32 acc, fp16 out).
// grid (391, 4): blockIdx.y 0,1 -> Yh cols 0/128; 2,3 -> Zh cols 0/128 (+bias).
// 8 warps: wm = wid>>1 (4 x 32 rows), wn = wid&1 (2 x 64 cols).
// K = 256 = 4 chunks of 64; SMEM: 2 stages x (A 16KB + B 16KB) = 64KB.
#define GEMM_SMEM_TOTAL (2 * 32768)
#define K_CHUNKS 4

__device__ __forceinline__ void load_chunk_cp(uint32_t sdst, int c, int bm, int nb,
                                              const __half* __restrict__ Ah,
                                              const __half* __restrict__ Bh) {
    int tid = threadIdx.x;
    #pragma unroll
    for (int i = 0; i < 4; i++) {                  // A: 128 rows x 128B
        int v = tid + i * 256;
        int r = v >> 3, kc = v & 7;
        const void* g = Ah + (size_t)(bm + r) * 256 + c * 64 + kc * 8;
        cp16(sdst + SWZ(r * 128 + kc * 16), g);
    }
    uint32_t bdst = sdst + 16384;
    #pragma unroll
    for (int i = 0; i < 4; i++) {                  // B: 128 n-rows x 128B
        int v = tid + i * 256;
        int r = v >> 3, kc = v & 7;
        const void* g = Bh + (size_t)(nb * 128 + r) * 256 + c * 64 + kc * 8;
        cp16(bdst + SWZ(r * 128 + kc * 16), g);
    }
}

__global__ __launch_bounds__(256)
void gemm_tc_kernel(const __half* __restrict__ Ah, const __half* __restrict__ Bh,
                    const float* __restrict__ bias, __half* __restrict__ Yh, __half* __restrict__ Zh) {
    extern __shared__ char smem[];
    uint32_t sb = smem_u32(smem);
    int tid = threadIdx.x, wid = tid >> 5, lane = tid & 31;
    int bm = blockIdx.x * 128;
    int nb = blockIdx.y;
    int wm = wid >> 1, wn = wid & 1;

    float acc[2][8][4];
    #pragma unroll
    for (int t = 0; t < 2; t++)
        #pragma unroll
        for (int u = 0; u < 8; u++)
            #pragma unroll
            for (int e = 0; e < 4; e++) acc[t][u][e] = 0.f;

    load_chunk_cp(sb, 0, bm, nb, Ah, Bh);
    cp_commit();

    for (int ch = 0; ch < K_CHUNKS; ch++) {
        int st = ch & 1;
        if (ch + 1 < K_CHUNKS) {
            load_chunk_cp(sb + (st ^ 1) * 32768, ch + 1, bm, nb, Ah, Bh);
            cp_commit();
            cp_wait1();
        } else {
            cp_wait0();
        }
        __syncthreads();

        uint32_t As = sb + st * 32768;
        uint32_t Bs = As + 16384;
        #pragma unroll
        for (int s = 0; s < 4; s++) {
            uint32_t a[2][4], bfrag[4][4];
            #pragma unroll
            for (int t = 0; t < 2; t++) {
                int m_local = wm * 32 + t * 16 + ((lane >> 3) & 1) * 8 + (lane & 7);
                int kseg = s * 2 + (lane >> 4);
                ldmx4(a[t], As + SWZ(m_local * 128 + kseg * 16));
            }
            #pragma unroll
            for (int j = 0; j < 4; j++) {
                int n_local = wn * 64 + (2 * j + (lane >> 4)) * 8 + (lane & 7);
                int kseg = s * 2 + ((lane >> 3) & 1);
                ldmx4(bfrag[j], Bs + SWZ(n_local * 128 + kseg * 16));
            }
            #pragma unroll
            for (int t = 0; t < 2; t++)
                #pragma unroll
                for (int u = 0; u < 8; u++)
                    mma16816(acc[t][u], a[t], bfrag[u >> 1][(u & 1) * 2],
                             bfrag[u >> 1][(u & 1) * 2 + 1]);
        }
        __syncthreads();
    }

    // epilogue (fp16 outputs)
    bool isY = (nb < 2);
    __half* C = isY ? Yh : Zh;
    int colbase = (nb & 1) * 128 + wn * 64;
    #pragma unroll
    for (int t = 0; t < 2; t++) {
        int m0 = bm + wm * 32 + t * 16 + (lane >> 2);
        #pragma unroll
        for (int u = 0; u < 8; u++) {
            int col = colbase + u * 8 + (lane & 3) * 2;
            float v0 = acc[t][u][0], v1 = acc[t][u][1];
            float v2 = acc[t][u][2], v3 = acc[t][u][3];
            if (!isY) {
                float2 bb = *(const float2*)(bias + col);
                v0 += bb.x; v1 += bb.y; v2 += bb.x; v3 += bb.y;
            }
            if (m0 < NN)     *(__half2*)(C + (size_t)m0 * 256 + col)       = __floats2half2_rn(v0, v1);
            if (m0 + 8 < NN) *(__half2*)(C + (size_t)(m0 + 8) * 256 + col) = __floats2half2_rn(v2, v3);
        }
    }
}

// ------ aggregation: out = relu(gather_sum(Yh) + Zh) — exact R10 body --------
// Ahout != nullptr: fp16 out (layers 1..5). F32out != nullptr: fp32 out (last
// layer; final activations exceed fp16 range — see R11 post-mortem).
__global__ void aggregate_relu_kernel(const __half* __restrict__ Yh, const __half* __restrict__ Zh,
                                      const int* __restrict__ rowptr, const int* __restrict__ csr,
                                      __half* __restrict__ Ahout, float* __restrict__ F32out,
                                      int n) {
    int warp = (blockIdx.x * blockDim.x + threadIdx.x) >> 5;
    int lane = threadIdx.x & 31;
    if (warp >= n) return;
    int beg = rowptr[warp], end = rowptr[warp + 1];
    size_t off = (size_t)warp * HH + lane * 8;

    float4 acc0, acc1;
    {
        uint4 q = *(const uint4*)(Zh + off);
        float2 f0 = __half22float2(*(__half2*)&q.x);
        float2 f1 = __half22float2(*(__half2*)&q.y);
        float2 f2 = __half22float2(*(__half2*)&q.z);
        float2 f3 = __half22float2(*(__half2*)&q.w);
        acc0 = make_float4(f0.x, f0.y, f1.x, f1.y);
        acc1 = make_float4(f2.x, f2.y, f3.x, f3.y);
    }
    for (int e = beg; e < end; e++) {
        int s0 = csr[e];
        uint4 q = *(const uint4*)(Yh + (size_t)s0 * HH + lane * 8);   // 8 halves
        float2 f0 = __half22float2(*(__half2*)&q.x);
        float2 f1 = __half22float2(*(__half2*)&q.y);
        float2 f2 = __half22float2(*(__half2*)&q.z);
        float2 f3 = __half22float2(*(__half2*)&q.w);
        acc0.x += f0.x; acc0.y += f0.y; acc0.z += f1.x; acc0.w += f1.y;
        acc1.x += f2.x; acc1.y += f2.y; acc1.z += f3.x; acc1.w += f3.y;
    }
    acc0.x = fmaxf(acc0.x, 0.f); acc0.y = fmaxf(acc0.y, 0.f);
    acc0.z = fmaxf(acc0.z, 0.f); acc0.w = fmaxf(acc0.w, 0.f);
    acc1.x = fmaxf(acc1.x, 0.f); acc1.y = fmaxf(acc1.y, 0.f);
    acc1.z = fmaxf(acc1.z, 0.f); acc1.w = fmaxf(acc1.w, 0.f);

    if (F32out) {
        *(float4*)(F32out + off)     = acc0;
        *(float4*)(F32out + off + 4) = acc1;
    }
    if (Ahout) {
        uint4 o;
        *(__half2*)&o.x = __floats2half2_rn(acc0.x, acc0.y);
        *(__half2*)&o.y = __floats2half2_rn(acc0.z, acc0.w);
        *(__half2*)&o.z = __floats2half2_rn(acc1.x, acc1.y);
        *(__half2*)&o.w = __floats2half2_rn(acc1.z, acc1.w);
        *(uint4*)(Ahout + off) = o;
    }
}

// ------- fused mean-pool + head: block g -> out[g][0..23] --------------------
__device__ __forceinline__ int lower_bound_dev(const int* a, int n, int key) {
    int lo = 0, hi = n;
    while (lo < hi) {
        int mid = (lo + hi) >> 1;
        if (a[mid] < key) lo = mid + 1; else hi = mid;
    }
    return lo;
}

__global__ void pool_head_kernel(const float* __restrict__ H, const int* __restrict__ batch,
                                 const float* __restrict__ w_out, const float* __restrict__ b_out,
                                 float* __restrict__ out, int n) {
    int g = blockIdx.x;
    int j = threadIdx.x;  // 256
    __shared__ int s_lo, s_hi;
    __shared__ float s_pool[HH];
    if (j == 0) {
        s_lo = lower_bound_dev(batch, n, g);
        s_hi = lower_bound_dev(batch, n, g + 1);
    }
    __syncthreads();
    int lo = s_lo, hi = s_hi;
    float acc = 0.f;
    for (int nd = lo; nd < hi; nd++) acc += H[(size_t)nd * HH + j];
    int cnt = hi - lo;
    s_pool[j] = acc / (float)max(cnt, 1);
    __syncthreads();
    if (j < OUTD) {
        float o = b_out[j];
        #pragma unroll 8
        for (int k = 0; k < HH; k++)
            o += s_pool[k] * w_out[k * OUTD + j];
        out[g * OUTD + j] = o;
    }
}

// ---------------- launch -----------------------------------------------------
extern "C" void kernel_launch(void* const* d_in, const int* in_sizes, int n_in,
                              void* d_out, int out_size) {
    const float* x       = (const float*)d_in[0];
    const int*   ei      = (const int*)d_in[1];
    const int*   batch   = (const int*)d_in[2];
    const float* w_rel1  = (const float*)d_in[3];
    const float* w_root1 = (const float*)d_in[4];
    const float* b1      = (const float*)d_in[5];
    const float* w_rel   = (const float*)d_in[6];   // 6 x 256 x 256
    const float* w_root  = (const float*)d_in[7];
    const float* b       = (const float*)d_in[8];   // 6 x 256
    const float* w_out   = (const float*)d_in[9];
    const float* b_out   = (const float*)d_in[10];
    float* out = (float*)d_out;

    const int* src = ei;        // edge_index[0]
    const int* dst = ei + EE;   // edge_index[1]

    float *hf, *agg3;
    __half *yh, *zh, *Ah, *Bh;
    int *deg, *rowptr, *cursor, *csr, *bsums;
    cudaGetSymbolAddress((void**)&hf, g_hf);
    cudaGetSymbolAddress((void**)&yh, g_yh);
    cudaGetSymbolAddress((void**)&zh, g_zh);
    cudaGetSymbolAddress((void**)&agg3, g_agg3);
    cudaGetSymbolAddress((void**)&deg, g_deg);
    cudaGetSymbolAddress((void**)&rowptr, g_rowptr);
    cudaGetSymbolAddress((void**)&cursor, g_cursor);
    cudaGetSymbolAddress((void**)&csr, g_csr);
    cudaGetSymbolAddress((void**)&bsums, g_bsums);
    cudaGetSymbolAddress((void**)&Ah, g_Ah);
    cudaGetSymbolAddress((void**)&Bh, g_Bh);

    cudaFuncSetAttribute(gemm_tc_kernel, cudaFuncAttributeMaxDynamicSharedMemorySize, GEMM_SMEM_TOTAL);

    // ---- build CSR (once per launch) ----
    zero2_kernel<<<(NN + 255) / 256, 256>>>(deg, cursor, NN);
    count_deg_kernel<<<(EE + 255) / 256, 256>>>(dst, deg, EE);
    scan_pass1<<<SCAN_BLOCKS, 256>>>(deg, bsums, NN);
    scan_pass2<<<1, 256>>>(bsums, SCAN_BLOCKS);
    scan_pass3<<<SCAN_BLOCKS, 256>>>(deg, bsums, rowptr, NN);
    fill_csr_kernel<<<(EE + 255) / 256, 256>>>(src, dst, rowptr, cursor, csr, EE);

    // ---- weight prep (fp16, K-major) ----
    prep_weights_kernel<<<(6 * 512 * 256 + 255) / 256, 256>>>(w_rel, w_root, Bh);

    // ---- layer 1 (3 -> 256), fp32 -> Ah fp16 directly ----
    aggx_kernel<<<(NN + 255) / 256, 256>>>(x, rowptr, csr, agg3, NN);
    layer1_kernel<<<NN, 256>>>(x, agg3, w_rel1, w_root1, b1, Ah);

    // ---- layers 2..7 (256 -> 256), tensor cores via mma.sync fp16 ----
    dim3 ggrid(NPAD / 128, 4);
    for (int i = 0; i < 6; i++) {
        gemm_tc_kernel<<<ggrid, 256, GEMM_SMEM_TOTAL>>>(Ah, Bh + (size_t)i * 512 * 256,
                                                        b + i * HH, yh, zh);
        bool last = (i == 5);
        aggregate_relu_kernel<<<(NN * 32 + 255) / 256, 256>>>(
            yh, zh, rowptr, csr,
            last ? (__half*)nullptr : Ah,
            last ? hf : (float*)nullptr, NN);
    }

    // ---- fused pool + head (reads fp32 hf — final layer exceeds fp16 range) --
    pool_head_kernel<<<GG, 256>>>(hf, batch, w_out, b_out, out, NN);
}

// round 15
// speedup vs baseline: 1.0471x; 1.0078x over previous
#include <cuda_runtime.h>
#include <cuda_bf16.h>
#include <cuda_fp16.h>
#include <cstdint>

// Problem constants (fixed by the dataset)
#define NN   50000
#define NPAD 50048        // 391 * 128
#define EE   800000
#define FIN  3
#define HH   256
#define GG   64
#define OUTD 24

// ---------------- scratch (device globals; no allocation allowed) -----------
__device__ float g_hf[NN * HH];           // final-layer fp32 activations (range > fp16 max!)
__device__ __half g_yh[(size_t)NN * HH];  // h @ w_rel, fp16 (gather payload)
__device__ __half g_zh[(size_t)NN * HH];  // h @ w_root + b, fp16
__device__ float g_agg3[NN * FIN];
__device__ int   g_deg[NN + 1];
__device__ int   g_rowptr[NN + 1];
__device__ int   g_cursor[NN + 1];
__device__ int   g_csr[EE];
__device__ int   g_bsums[256];
// tensor-core path scratch (single fp16, no hi/lo split)
__device__ __half g_Ah[(size_t)NPAD * 256];            // activations, fp16 (pad rows: zero)
__device__ __half g_Bh[(size_t)6 * 512 * 256];         // per layer: [n(512)][k(256)] fp16, K-major

// ---------------- PTX helpers (family-safe only: mma.sync / ldmatrix / cp.async)
__device__ __forceinline__ uint32_t smem_u32(const void* p) {
    uint32_t a;
    asm("{ .reg .u64 t; cvta.to.shared.u64 t, %1; cvt.u32.u64 %0, t; }" : "=r"(a) : "l"(p));
    return a;
}
__device__ __forceinline__ void cp16(uint32_t saddr, const void* gptr) {
    asm volatile("cp.async.cg.shared.global [%0], [%1], 16;" :: "r"(saddr), "l"(gptr) : "memory");
}
__device__ __forceinline__ void cp_commit() {
    asm volatile("cp.async.commit_group;" ::: "memory");
}
__device__ __forceinline__ void cp_wait2() {
    asm volatile("cp.async.wait_group 2;" ::: "memory");
}
__device__ __forceinline__ void cp_wait1() {
    asm volatile("cp.async.wait_group 1;" ::: "memory");
}
__device__ __forceinline__ void cp_wait0() {
    asm volatile("cp.async.wait_group 0;" ::: "memory");
}
__device__ __forceinline__ void ldmx4(uint32_t* r, uint32_t addr) {
    asm volatile("ldmatrix.sync.aligned.m8n8.x4.shared.b16 {%0,%1,%2,%3}, [%4];"
                 : "=r"(r[0]), "=r"(r[1]), "=r"(r[2]), "=r"(r[3]) : "r"(addr));
}
__device__ __forceinline__ void mma16816(float* c, const uint32_t* a, uint32_t b0, uint32_t b1) {
    asm volatile(
        "mma.sync.aligned.m16n8k16.row.col.f32.f16.f16.f32 "
        "{%0,%1,%2,%3}, {%4,%5,%6,%7}, {%8,%9}, {%0,%1,%2,%3};"
        : "+f"(c[0]), "+f"(c[1]), "+f"(c[2]), "+f"(c[3])
        : "r"(a[0]), "r"(a[1]), "r"(a[2]), "r"(a[3]), "r"(b0), "r"(b1));
}
// 128B-atom XOR swizzle (bank-conflict-free STS/ldmatrix)
__device__ __forceinline__ uint32_t SWZ(uint32_t x) { return x ^ ((x >> 3) & 0x70); }

// ---------------- CSR construction ------------------------------------------
__global__ void zero2_kernel(int* a, int* b, int n) {
    int i = blockIdx.x * blockDim.x + threadIdx.x;
    if (i < n) { a[i] = 0; b[i] = 0; }
}

__global__ void count_deg_kernel(const int* __restrict__ dst, int* __restrict__ deg, int e) {
    int i = blockIdx.x * blockDim.x + threadIdx.x;
    if (i < e) atomicAdd(&deg[dst[i]], 1);
}

// ---- parallel exclusive scan over NN elems: 3 phases, 256-elem blocks ----
#define SCAN_BLOCKS ((NN + 255) / 256)   // 196

__global__ void scan_pass1(const int* __restrict__ deg, int* __restrict__ bsums, int n) {
    int i = blockIdx.x * 256 + threadIdx.x;
    int v = (i < n) ? deg[i] : 0;
    #pragma unroll
    for (int o = 16; o > 0; o >>= 1) v += __shfl_down_sync(0xFFFFFFFF, v, o);
    __shared__ int ws[8];
    int wid = threadIdx.x >> 5, lane = threadIdx.x & 31;
    if (lane == 0) ws[wid] = v;
    __syncthreads();
    if (threadIdx.x == 0) {
        int s = 0;
        #pragma unroll
        for (int w = 0; w < 8; w++) s += ws[w];
        bsums[blockIdx.x] = s;
    }
}

__global__ void scan_pass2(int* __restrict__ bsums, int nb) {
    __shared__ int sh[256];
    int tid = threadIdx.x;
    int v = (tid < nb) ? bsums[tid] : 0;
    sh[tid] = v;
    __syncthreads();
    #pragma unroll
    for (int off = 1; off < 256; off <<= 1) {
        int t = (tid >= off) ? sh[tid - off] : 0;
        __syncthreads();
        sh[tid] += t;
        __syncthreads();
    }
    if (tid < nb) bsums[tid] = sh[tid] - v;   // exclusive
}

__global__ void scan_pass3(const int* __restrict__ deg, const int* __restrict__ bsums,
                           int* __restrict__ rowptr, int n) {
    __shared__ int sh[256];
    int i = blockIdx.x * 256 + threadIdx.x;
    int tid = threadIdx.x;
    int v = (i < n) ? deg[i] : 0;
    sh[tid] = v;
    __syncthreads();
    #pragma unroll
    for (int off = 1; off < 256; off <<= 1) {
        int t = (tid >= off) ? sh[tid - off] : 0;
        __syncthreads();
        sh[tid] += t;
        __syncthreads();
    }
    int incl = sh[tid];
    int base = bsums[blockIdx.x];
    if (i < n)  rowptr[i] = base + incl - v;
    if (i == n - 1) rowptr[n] = base + incl;
}

__global__ void fill_csr_kernel(const int* __restrict__ src, const int* __restrict__ dst,
                                const int* __restrict__ rowptr, int* __restrict__ cursor,
                                int* __restrict__ csr, int e) {
    int i = blockIdx.x * blockDim.x + threadIdx.x;
    if (i < e) {
        int d = dst[i];
        int pos = atomicAdd(&cursor[d], 1);
        csr[rowptr[d] + pos] = src[i];
    }
}

// ---------------- layer 1 (F_IN=3 -> H), writes Ah fp16 directly -------------
__global__ void aggx_kernel(const float* __restrict__ x,
                            const int* __restrict__ rowptr, const int* __restrict__ csr,
                            float* __restrict__ agg3, int n) {
    int i = blockIdx.x * blockDim.x + threadIdx.x;
    if (i >= n) return;
    float a0 = 0.f, a1 = 0.f, a2 = 0.f;
    int beg = rowptr[i], end = rowptr[i + 1];
    for (int e = beg; e < end; e++) {
        int s = csr[e];
        a0 += x[s * 3 + 0];
        a1 += x[s * 3 + 1];
        a2 += x[s * 3 + 2];
    }
    agg3[i * 3 + 0] = a0;
    agg3[i * 3 + 1] = a1;
    agg3[i * 3 + 2] = a2;
}

__global__ void layer1_kernel(const float* __restrict__ x, const float* __restrict__ agg3,
                              const float* __restrict__ wr, const float* __restrict__ wro,
                              const float* __restrict__ b1, __half* __restrict__ Ah) {
    int n = blockIdx.x;
    int j = threadIdx.x;  // 256
    __shared__ float sx[3], sa[3];
    if (j < 3) { sx[j] = x[n * 3 + j]; sa[j] = agg3[n * 3 + j]; }
    __syncthreads();
    float v = b1[j];
    #pragma unroll
    for (int f = 0; f < 3; f++)
        v += sa[f] * wr[f * HH + j] + sx[f] * wro[f * HH + j];
    v = fmaxf(v, 0.f);
    Ah[(size_t)n * 256 + j] = __float2half_rn(v);
}

// ---------------- weight prep: fp32 [K,N] -> fp16 [N][256] K-major -----------
__global__ void prep_weights_kernel(const float* __restrict__ w_rel, const float* __restrict__ w_root,
                                    __half* __restrict__ Bh) {
    int idx = blockIdx.x * blockDim.x + threadIdx.x;
    if (idx >= 6 * 512 * 256) return;
    int k = idx & 255;
    int n = (idx >> 8) & 511;
    int L = idx >> 17;
    float w = (n < 256) ? w_rel[(size_t)L * 65536 + k * 256 + n]
                        : w_root[(size_t)L * 65536 + k * 256 + (n - 256)];
    Bh[(size_t)L * 512 * 256 + (size_t)n * 256 + k] = __float2half_rn(w);
}

// ---------------- mma.sync GEMM ----------------------------------------------
// C[128,128] per CTA; C = A[M,256] x B^T (fp16 in, fp32 acc, fp16 out).
// grid (391, 4): blockIdx.y 0,1 -> Yh cols 0/128; 2,3 -> Zh cols 0/128 (+bias).
// 8 warps: wm = wid>>1 (4 x 32 rows), wn = wid&1 (2 x 64 cols).
// K = 256 = 4 chunks of 64; SMEM: 3-stage ring x 32KB = 96KB (2 prefetches
// always in flight). 2 CTAs/SM (196KB smem, regs capped via launch_bounds).
#define GEMM_STAGE      32768
#define GEMM_SMEM_TOTAL (3 * GEMM_STAGE)
#define K_CHUNKS 4

__device__ __forceinline__ void load_chunk_cp(uint32_t sdst, int c, int bm, int nb,
                                              const __half* __restrict__ Ah,
                                              const __half* __restrict__ Bh) {
    int tid = threadIdx.x;
    #pragma unroll
    for (int i = 0; i < 4; i++) {                  // A: 128 rows x 128B
        int v = tid + i * 256;
        int r = v >> 3, kc = v & 7;
        const void* g = Ah + (size_t)(bm + r) * 256 + c * 64 + kc * 8;
        cp16(sdst + SWZ(r * 128 + kc * 16), g);
    }
    uint32_t bdst = sdst + 16384;
    #pragma unroll
    for (int i = 0; i < 4; i++) {                  // B: 128 n-rows x 128B
        int v = tid + i * 256;
        int r = v >> 3, kc = v & 7;
        const void* g = Bh + (size_t)(nb * 128 + r) * 256 + c * 64 + kc * 8;
        cp16(bdst + SWZ(r * 128 + kc * 16), g);
    }
}

__global__ __launch_bounds__(256, 2)
void gemm_tc_kernel(const __half* __restrict__ Ah, const __half* __restrict__ Bh,
                    const float* __restrict__ bias, __half* __restrict__ Yh, __half* __restrict__ Zh) {
    extern __shared__ char smem[];
    uint32_t sb = smem_u32(smem);
    int tid = threadIdx.x, wid = tid >> 5, lane = tid & 31;
    int bm = blockIdx.x * 128;
    int nb = blockIdx.y;
    int wm = wid >> 1, wn = wid & 1;

    float acc[2][8][4];
    #pragma unroll
    for (int t = 0; t < 2; t++)
        #pragma unroll
        for (int u = 0; u < 8; u++)
            #pragma unroll
            for (int e = 0; e < 4; e++) acc[t][u][e] = 0.f;

    // 3-stage prologue: chunks 0 and 1 in flight
    load_chunk_cp(sb + 0 * GEMM_STAGE, 0, bm, nb, Ah, Bh);
    cp_commit();
    load_chunk_cp(sb + 1 * GEMM_STAGE, 1, bm, nb, Ah, Bh);
    cp_commit();

    #pragma unroll
    for (int ch = 0; ch < K_CHUNKS; ch++) {
        if (ch + 2 < K_CHUNKS) {
            load_chunk_cp(sb + ((ch + 2) % 3) * GEMM_STAGE, ch + 2, bm, nb, Ah, Bh);
            cp_commit();
        }
        // wait until chunk ch's group is complete: pending <= min(2, 3-ch)
        switch (ch) {
            case 0: case 1: cp_wait2(); break;
            case 2:         cp_wait1(); break;
            default:        cp_wait0(); break;
        }
        __syncthreads();

        uint32_t As = sb + (ch % 3) * GEMM_STAGE;
        uint32_t Bs = As + 16384;
        #pragma unroll
        for (int s = 0; s < 4; s++) {
            uint32_t a[2][4], bfrag[4][4];
            #pragma unroll
            for (int t = 0; t < 2; t++) {
                int m_local = wm * 32 + t * 16 + ((lane >> 3) & 1) * 8 + (lane & 7);
                int kseg = s * 2 + (lane >> 4);
                ldmx4(a[t], As + SWZ(m_local * 128 + kseg * 16));
            }
            #pragma unroll
            for (int j = 0; j < 4; j++) {
                int n_local = wn * 64 + (2 * j + (lane >> 4)) * 8 + (lane & 7);
                int kseg = s * 2 + ((lane >> 3) & 1);
                ldmx4(bfrag[j], Bs + SWZ(n_local * 128 + kseg * 16));
            }
            #pragma unroll
            for (int t = 0; t < 2; t++)
                #pragma unroll
                for (int u = 0; u < 8; u++)
                    mma16816(acc[t][u], a[t], bfrag[u >> 1][(u & 1) * 2],
                             bfrag[u >> 1][(u & 1) * 2 + 1]);
        }
        __syncthreads();   // all warps done reading buf[ch%3] before it's refilled
    }

    // epilogue (fp16 outputs)
    bool isY = (nb < 2);
    __half* C = isY ? Yh : Zh;
    int colbase = (nb & 1) * 128 + wn * 64;
    #pragma unroll
    for (int t = 0; t < 2; t++) {
        int m0 = bm + wm * 32 + t * 16 + (lane >> 2);
        #pragma unroll
        for (int u = 0; u < 8; u++) {
            int col = colbase + u * 8 + (lane & 3) * 2;
            float v0 = acc[t][u][0], v1 = acc[t][u][1];
            float v2 = acc[t][u][2], v3 = acc[t][u][3];
            if (!isY) {
                float2 bb = *(const float2*)(bias + col);
                v0 += bb.x; v1 += bb.y; v2 += bb.x; v3 += bb.y;
            }
            if (m0 < NN)     *(__half2*)(C + (size_t)m0 * 256 + col)       = __floats2half2_rn(v0, v1);
            if (m0 + 8 < NN) *(__half2*)(C + (size_t)(m0 + 8) * 256 + col) = __floats2half2_rn(v2, v3);
        }
    }
}

// ------ aggregation: out = relu(gather_sum(Yh) + Zh) — exact R10 body --------
// Ahout != nullptr: fp16 out (layers 1..5). F32out != nullptr: fp32 out (last
// layer; final activations exceed fp16 range — see R11 post-mortem).
__global__ void aggregate_relu_kernel(const __half* __restrict__ Yh, const __half* __restrict__ Zh,
                                      const int* __restrict__ rowptr, const int* __restrict__ csr,
                                      __half* __restrict__ Ahout, float* __restrict__ F32out,
                                      int n) {
    int warp = (blockIdx.x * blockDim.x + threadIdx.x) >> 5;
    int lane = threadIdx.x & 31;
    if (warp >= n) return;
    int beg = rowptr[warp], end = rowptr[warp + 1];
    size_t off = (size_t)warp * HH + lane * 8;

    float4 acc0, acc1;
    {
        uint4 q = *(const uint4*)(Zh + off);
        float2 f0 = __half22float2(*(__half2*)&q.x);
        float2 f1 = __half22float2(*(__half2*)&q.y);
        float2 f2 = __half22float2(*(__half2*)&q.z);
        float2 f3 = __half22float2(*(__half2*)&q.w);
        acc0 = make_float4(f0.x, f0.y, f1.x, f1.y);
        acc1 = make_float4(f2.x, f2.y, f3.x, f3.y);
    }
    for (int e = beg; e < end; e++) {
        int s0 = csr[e];
        uint4 q = *(const uint4*)(Yh + (size_t)s0 * HH + lane * 8);   // 8 halves
        float2 f0 = __half22float2(*(__half2*)&q.x);
        float2 f1 = __half22float2(*(__half2*)&q.y);
        float2 f2 = __half22float2(*(__half2*)&q.z);
        float2 f3 = __half22float2(*(__half2*)&q.w);
        acc0.x += f0.x; acc0.y += f0.y; acc0.z += f1.x; acc0.w += f1.y;
        acc1.x += f2.x; acc1.y += f2.y; acc1.z += f3.x; acc1.w += f3.y;
    }
    acc0.x = fmaxf(acc0.x, 0.f); acc0.y = fmaxf(acc0.y, 0.f);
    acc0.z = fmaxf(acc0.z, 0.f); acc0.w = fmaxf(acc0.w, 0.f);
    acc1.x = fmaxf(acc1.x, 0.f); acc1.y = fmaxf(acc1.y, 0.f);
    acc1.z = fmaxf(acc1.z, 0.f); acc1.w = fmaxf(acc1.w, 0.f);

    if (F32out) {
        *(float4*)(F32out + off)     = acc0;
        *(float4*)(F32out + off + 4) = acc1;
    }
    if (Ahout) {
        uint4 o;
        *(__half2*)&o.x = __floats2half2_rn(acc0.x, acc0.y);
        *(__half2*)&o.y = __floats2half2_rn(acc0.z, acc0.w);
        *(__half2*)&o.z = __floats2half2_rn(acc1.x, acc1.y);
        *(__half2*)&o.w = __floats2half2_rn(acc1.z, acc1.w);
        *(uint4*)(Ahout + off) = o;
    }
}

// ------- fused mean-pool + head: block g -> out[g][0..23] --------------------
__device__ __forceinline__ int lower_bound_dev(const int* a, int n, int key) {
    int lo = 0, hi = n;
    while (lo < hi) {
        int mid = (lo + hi) >> 1;
        if (a[mid] < key) lo = mid + 1; else hi = mid;
    }
    return lo;
}

__global__ void pool_head_kernel(const float* __restrict__ H, const int* __restrict__ batch,
                                 const float* __restrict__ w_out, const float* __restrict__ b_out,
                                 float* __restrict__ out, int n) {
    int g = blockIdx.x;
    int j = threadIdx.x;  // 256
    __shared__ int s_lo, s_hi;
    __shared__ float s_pool[HH];
    if (j == 0) {
        s_lo = lower_bound_dev(batch, n, g);
        s_hi = lower_bound_dev(batch, n, g + 1);
    }
    __syncthreads();
    int lo = s_lo, hi = s_hi;
    float acc = 0.f;
    for (int nd = lo; nd < hi; nd++) acc += H[(size_t)nd * HH + j];
    int cnt = hi - lo;
    s_pool[j] = acc / (float)max(cnt, 1);
    __syncthreads();
    if (j < OUTD) {
        float o = b_out[j];
        #pragma unroll 8
        for (int k = 0; k < HH; k++)
            o += s_pool[k] * w_out[k * OUTD + j];
        out[g * OUTD + j] = o;
    }
}

// ---------------- launch -----------------------------------------------------
extern "C" void kernel_launch(void* const* d_in, const int* in_sizes, int n_in,
                              void* d_out, int out_size) {
    const float* x       = (const float*)d_in[0];
    const int*   ei      = (const int*)d_in[1];
    const int*   batch   = (const int*)d_in[2];
    const float* w_rel1  = (const float*)d_in[3];
    const float* w_root1 = (const float*)d_in[4];
    const float* b1      = (const float*)d_in[5];
    const float* w_rel   = (const float*)d_in[6];   // 6 x 256 x 256
    const float* w_root  = (const float*)d_in[7];
    const float* b       = (const float*)d_in[8];   // 6 x 256
    const float* w_out   = (const float*)d_in[9];
    const float* b_out   = (const float*)d_in[10];
    float* out = (float*)d_out;

    const int* src = ei;        // edge_index[0]
    const int* dst = ei + EE;   // edge_index[1]

    float *hf, *agg3;
    __half *yh, *zh, *Ah, *Bh;
    int *deg, *rowptr, *cursor, *csr, *bsums;
    cudaGetSymbolAddress((void**)&hf, g_hf);
    cudaGetSymbolAddress((void**)&yh, g_yh);
    cudaGetSymbolAddress((void**)&zh, g_zh);
    cudaGetSymbolAddress((void**)&agg3, g_agg3);
    cudaGetSymbolAddress((void**)&deg, g_deg);
    cudaGetSymbolAddress((void**)&rowptr, g_rowptr);
    cudaGetSymbolAddress((void**)&cursor, g_cursor);
    cudaGetSymbolAddress((void**)&csr, g_csr);
    cudaGetSymbolAddress((void**)&bsums, g_bsums);
    cudaGetSymbolAddress((void**)&Ah, g_Ah);
    cudaGetSymbolAddress((void**)&Bh, g_Bh);

    cudaFuncSetAttribute(gemm_tc_kernel, cudaFuncAttributeMaxDynamicSharedMemorySize, GEMM_SMEM_TOTAL);

    // ---- build CSR (once per launch) ----
    zero2_kernel<<<(NN + 255) / 256, 256>>>(deg, cursor, NN);
    count_deg_kernel<<<(EE + 255) / 256, 256>>>(dst, deg, EE);
    scan_pass1<<<SCAN_BLOCKS, 256>>>(deg, bsums, NN);
    scan_pass2<<<1, 256>>>(bsums, SCAN_BLOCKS);
    scan_pass3<<<SCAN_BLOCKS, 256>>>(deg, bsums, rowptr, NN);
    fill_csr_kernel<<<(EE + 255) / 256, 256>>>(src, dst, rowptr, cursor, csr, EE);

    // ---- weight prep (fp16, K-major) ----
    prep_weights_kernel<<<(6 * 512 * 256 + 255) / 256, 256>>>(w_rel, w_root, Bh);

    // ---- layer 1 (3 -> 256), fp32 -> Ah fp16 directly ----
    aggx_kernel<<<(NN + 255) / 256, 256>>>(x, rowptr, csr, agg3, NN);
    layer1_kernel<<<NN, 256>>>(x, agg3, w_rel1, w_root1, b1, Ah);

    // ---- layers 2..7 (256 -> 256), tensor cores via mma.sync fp16 ----
    dim3 ggrid(NPAD / 128, 4);
    for (int i = 0; i < 6; i++) {
        gemm_tc_kernel<<<ggrid, 256, GEMM_SMEM_TOTAL>>>(Ah, Bh + (size_t)i * 512 * 256,
                                                        b + i * HH, yh, zh);
        bool last = (i == 5);
        aggregate_relu_kernel<<<(NN * 32 + 255) / 256, 256>>>(
            yh, zh, rowptr, csr,
            last ? (__half*)nullptr : Ah,
            last ? hf : (float*)nullptr, NN);
    }

    // ---- fused pool + head (reads fp32 hf — final layer exceeds fp16 range) --
    pool_head_kernel<<<GG, 256>>>(hf, batch, w_out, b_out, out, NN);
}

// round 16
// speedup vs baseline: 1.0614x; 1.0137x over previous
#include <cuda_runtime.h>
#include <cuda_bf16.h>
#include <cuda_fp16.h>
#include <cstdint>

// Problem constants (fixed by the dataset)
#define NN   50000
#define NPAD 50048        // 391 * 128
#define EE   800000
#define FIN  3
#define HH   256
#define GG   64
#define OUTD 24

// ---------------- scratch (device globals; no allocation allowed) -----------
__device__ float g_hf[NN * HH];           // final-layer fp32 activations (range > fp16 max!)
__device__ __half g_yh[(size_t)NN * HH];  // h @ w_rel, fp16 (gather payload)
__device__ __half g_zh[(size_t)NN * HH];  // h @ w_root + b, fp16
__device__ float g_agg3[NN * FIN];
__device__ int   g_deg[NN + 1];
__device__ int   g_rowptr[NN + 1];
__device__ int   g_cursor[NN + 1];
__device__ int   g_csr[EE];
__device__ int   g_bsums[256];
// tensor-core path scratch (single fp16, no hi/lo split)
__device__ __half g_Ah[(size_t)NPAD * 256];            // activations, fp16 (pad rows: zero)
__device__ __half g_Bh[(size_t)6 * 512 * 256];         // per layer: [n(512)][k(256)] fp16, K-major

// ---------------- PTX helpers (family-safe only: mma.sync / ldmatrix / cp.async)
__device__ __forceinline__ uint32_t smem_u32(const void* p) {
    uint32_t a;
    asm("{ .reg .u64 t; cvta.to.shared.u64 t, %1; cvt.u32.u64 %0, t; }" : "=r"(a) : "l"(p));
    return a;
}
__device__ __forceinline__ void cp16(uint32_t saddr, const void* gptr) {
    asm volatile("cp.async.cg.shared.global [%0], [%1], 16;" :: "r"(saddr), "l"(gptr) : "memory");
}
__device__ __forceinline__ void cp_commit() {
    asm volatile("cp.async.commit_group;" ::: "memory");
}
__device__ __forceinline__ void cp_wait2() {
    asm volatile("cp.async.wait_group 2;" ::: "memory");
}
__device__ __forceinline__ void cp_wait1() {
    asm volatile("cp.async.wait_group 1;" ::: "memory");
}
__device__ __forceinline__ void cp_wait0() {
    asm volatile("cp.async.wait_group 0;" ::: "memory");
}
__device__ __forceinline__ void ldmx4(uint32_t* r, uint32_t addr) {
    asm volatile("ldmatrix.sync.aligned.m8n8.x4.shared.b16 {%0,%1,%2,%3}, [%4];"
                 : "=r"(r[0]), "=r"(r[1]), "=r"(r[2]), "=r"(r[3]) : "r"(addr));
}
__device__ __forceinline__ void mma16816(float* c, const uint32_t* a, uint32_t b0, uint32_t b1) {
    asm volatile(
        "mma.sync.aligned.m16n8k16.row.col.f32.f16.f16.f32 "
        "{%0,%1,%2,%3}, {%4,%5,%6,%7}, {%8,%9}, {%0,%1,%2,%3};"
        : "+f"(c[0]), "+f"(c[1]), "+f"(c[2]), "+f"(c[3])
        : "r"(a[0]), "r"(a[1]), "r"(a[2]), "r"(a[3]), "r"(b0), "r"(b1));
}
// 128B-atom XOR swizzle (bank-conflict-free STS/ldmatrix)
__device__ __forceinline__ uint32_t SWZ(uint32_t x) { return x ^ ((x >> 3) & 0x70); }

// ---------------- CSR construction ------------------------------------------
__global__ void zero2_kernel(int* a, int* b, int n) {
    int i = blockIdx.x * blockDim.x + threadIdx.x;
    if (i < n) { a[i] = 0; b[i] = 0; }
}

__global__ void count_deg_kernel(const int* __restrict__ dst, int* __restrict__ deg, int e) {
    int i = blockIdx.x * blockDim.x + threadIdx.x;
    if (i < e) atomicAdd(&deg[dst[i]], 1);
}

// ---- parallel exclusive scan over NN elems: 2 phases, 256-elem blocks ----
#define SCAN_BLOCKS ((NN + 255) / 256)   // 196

__global__ void scan_pass1(const int* __restrict__ deg, int* __restrict__ bsums, int n) {
    int i = blockIdx.x * 256 + threadIdx.x;
    int v = (i < n) ? deg[i] : 0;
    #pragma unroll
    for (int o = 16; o > 0; o >>= 1) v += __shfl_down_sync(0xFFFFFFFF, v, o);
    __shared__ int ws[8];
    int wid = threadIdx.x >> 5, lane = threadIdx.x & 31;
    if (lane == 0) ws[wid] = v;
    __syncthreads();
    if (threadIdx.x == 0) {
        int s = 0;
        #pragma unroll
        for (int w = 0; w < 8; w++) s += ws[w];
        bsums[blockIdx.x] = s;
    }
}

// pass3 also computes its own exclusive prefix of bsums (196 elems, cheap)
__global__ void scan_pass3(const int* __restrict__ deg, const int* __restrict__ bsums,
                           int* __restrict__ rowptr, int n, int nb) {
    __shared__ int sh[256];
    __shared__ int s_base;
    int i = blockIdx.x * 256 + threadIdx.x;
    int tid = threadIdx.x;

    // block-local prefix of bsums[0..blockIdx.x): warp 0 reduces
    if (tid < 32) {
        int s = 0;
        for (int j = tid; j < blockIdx.x; j += 32) s += bsums[j];
        #pragma unroll
        for (int o = 16; o > 0; o >>= 1) s += __shfl_down_sync(0xFFFFFFFF, s, o);
        if (tid == 0) s_base = s;
    }

    int v = (i < n) ? deg[i] : 0;
    sh[tid] = v;
    __syncthreads();
    #pragma unroll
    for (int off = 1; off < 256; off <<= 1) {
        int t = (tid >= off) ? sh[tid - off] : 0;
        __syncthreads();
        sh[tid] += t;
        __syncthreads();
    }
    int incl = sh[tid];
    int base = s_base;
    if (i < n)  rowptr[i] = base + incl - v;
    if (i == n - 1) rowptr[n] = base + incl;
}

__global__ void fill_csr_kernel(const int* __restrict__ src, const int* __restrict__ dst,
                                const int* __restrict__ rowptr, int* __restrict__ cursor,
                                int* __restrict__ csr, int e) {
    int i = blockIdx.x * blockDim.x + threadIdx.x;
    if (i < e) {
        int d = dst[i];
        int pos = atomicAdd(&cursor[d], 1);
        csr[rowptr[d] + pos] = src[i];
    }
}

// ---------------- layer 1 (F_IN=3 -> H), writes Ah fp16 directly -------------
__global__ void aggx_kernel(const float* __restrict__ x,
                            const int* __restrict__ rowptr, const int* __restrict__ csr,
                            float* __restrict__ agg3, int n) {
    int i = blockIdx.x * blockDim.x + threadIdx.x;
    if (i >= n) return;
    float a0 = 0.f, a1 = 0.f, a2 = 0.f;
    int beg = rowptr[i], end = rowptr[i + 1];
    for (int e = beg; e < end; e++) {
        int s = csr[e];
        a0 += x[s * 3 + 0];
        a1 += x[s * 3 + 1];
        a2 += x[s * 3 + 2];
    }
    agg3[i * 3 + 0] = a0;
    agg3[i * 3 + 1] = a1;
    agg3[i * 3 + 2] = a2;
}

__global__ void layer1_kernel(const float* __restrict__ x, const float* __restrict__ agg3,
                              const float* __restrict__ wr, const float* __restrict__ wro,
                              const float* __restrict__ b1, __half* __restrict__ Ah) {
    int n = blockIdx.x;
    int j = threadIdx.x;  // 256
    __shared__ float sx[3], sa[3];
    if (j < 3) { sx[j] = x[n * 3 + j]; sa[j] = agg3[n * 3 + j]; }
    __syncthreads();
    float v = b1[j];
    #pragma unroll
    for (int f = 0; f < 3; f++)
        v += sa[f] * wr[f * HH + j] + sx[f] * wro[f * HH + j];
    v = fmaxf(v, 0.f);
    Ah[(size_t)n * 256 + j] = __float2half_rn(v);
}

// ---------------- weight prep: fp32 [K,N] -> fp16 [N][256] K-major -----------
__global__ void prep_weights_kernel(const float* __restrict__ w_rel, const float* __restrict__ w_root,
                                    __half* __restrict__ Bh) {
    int idx = blockIdx.x * blockDim.x + threadIdx.x;
    if (idx >= 6 * 512 * 256) return;
    int k = idx & 255;
    int n = (idx >> 8) & 511;
    int L = idx >> 17;
    float w = (n < 256) ? w_rel[(size_t)L * 65536 + k * 256 + n]
                        : w_root[(size_t)L * 65536 + k * 256 + (n - 256)];
    Bh[(size_t)L * 512 * 256 + (size_t)n * 256 + k] = __float2half_rn(w);
}

// ---------------- mma.sync GEMM ----------------------------------------------
// C[128,128] per CTA; C = A[M,256] x B^T (fp16 in, fp32 acc, fp16 out).
// grid (391, 4): blockIdx.y 0,1 -> Yh cols 0/128; 2,3 -> Zh cols 0/128 (+bias).
// 8 warps: wm = wid>>1 (4 x 32 rows), wn = wid&1 (2 x 64 cols).
// K = 256 = 4 chunks of 64; SMEM: 3-stage ring x 32KB = 96KB.
#define GEMM_STAGE      32768
#define GEMM_SMEM_TOTAL (3 * GEMM_STAGE)
#define K_CHUNKS 4

__device__ __forceinline__ void load_chunk_cp(uint32_t sdst, int c, int bm, int nb,
                                              const __half* __restrict__ Ah,
                                              const __half* __restrict__ Bh) {
    int tid = threadIdx.x;
    #pragma unroll
    for (int i = 0; i < 4; i++) {                  // A: 128 rows x 128B
        int v = tid + i * 256;
        int r = v >> 3, kc = v & 7;
        const void* g = Ah + (size_t)(bm + r) * 256 + c * 64 + kc * 8;
        cp16(sdst + SWZ(r * 128 + kc * 16), g);
    }
    uint32_t bdst = sdst + 16384;
    #pragma unroll
    for (int i = 0; i < 4; i++) {                  // B: 128 n-rows x 128B
        int v = tid + i * 256;
        int r = v >> 3, kc = v & 7;
        const void* g = Bh + (size_t)(nb * 128 + r) * 256 + c * 64 + kc * 8;
        cp16(bdst + SWZ(r * 128 + kc * 16), g);
    }
}

__global__ __launch_bounds__(256, 2)
void gemm_tc_kernel(const __half* __restrict__ Ah, const __half* __restrict__ Bh,
                    const float* __restrict__ bias, __half* __restrict__ Yh, __half* __restrict__ Zh) {
    extern __shared__ char smem[];
    uint32_t sb = smem_u32(smem);
    int tid = threadIdx.x, wid = tid >> 5, lane = tid & 31;
    int bm = blockIdx.x * 128;
    int nb = blockIdx.y;
    int wm = wid >> 1, wn = wid & 1;

    float acc[2][8][4];
    #pragma unroll
    for (int t = 0; t < 2; t++)
        #pragma unroll
        for (int u = 0; u < 8; u++)
            #pragma unroll
            for (int e = 0; e < 4; e++) acc[t][u][e] = 0.f;

    // 3-stage prologue: chunks 0 and 1 in flight
    load_chunk_cp(sb + 0 * GEMM_STAGE, 0, bm, nb, Ah, Bh);
    cp_commit();
    load_chunk_cp(sb + 1 * GEMM_STAGE, 1, bm, nb, Ah, Bh);
    cp_commit();

    #pragma unroll
    for (int ch = 0; ch < K_CHUNKS; ch++) {
        if (ch + 2 < K_CHUNKS) {
            load_chunk_cp(sb + ((ch + 2) % 3) * GEMM_STAGE, ch + 2, bm, nb, Ah, Bh);
            cp_commit();
        }
        switch (ch) {
            case 0: case 1: cp_wait2(); break;
            case 2:         cp_wait1(); break;
            default:        cp_wait0(); break;
        }
        __syncthreads();

        uint32_t As = sb + (ch % 3) * GEMM_STAGE;
        uint32_t Bs = As + 16384;
        #pragma unroll
        for (int s = 0; s < 4; s++) {
            uint32_t a[2][4], bfrag[4][4];
            #pragma unroll
            for (int t = 0; t < 2; t++) {
                int m_local = wm * 32 + t * 16 + ((lane >> 3) & 1) * 8 + (lane & 7);
                int kseg = s * 2 + (lane >> 4);
                ldmx4(a[t], As + SWZ(m_local * 128 + kseg * 16));
            }
            #pragma unroll
            for (int j = 0; j < 4; j++) {
                int n_local = wn * 64 + (2 * j + (lane >> 4)) * 8 + (lane & 7);
                int kseg = s * 2 + ((lane >> 3) & 1);
                ldmx4(bfrag[j], Bs + SWZ(n_local * 128 + kseg * 16));
            }
            #pragma unroll
            for (int t = 0; t < 2; t++)
                #pragma unroll
                for (int u = 0; u < 8; u++)
                    mma16816(acc[t][u], a[t], bfrag[u >> 1][(u & 1) * 2],
                             bfrag[u >> 1][(u & 1) * 2 + 1]);
        }
        __syncthreads();
    }

    // epilogue (fp16 outputs)
    bool isY = (nb < 2);
    __half* C = isY ? Yh : Zh;
    int colbase = (nb & 1) * 128 + wn * 64;
    #pragma unroll
    for (int t = 0; t < 2; t++) {
        int m0 = bm + wm * 32 + t * 16 + (lane >> 2);
        #pragma unroll
        for (int u = 0; u < 8; u++) {
            int col = colbase + u * 8 + (lane & 3) * 2;
            float v0 = acc[t][u][0], v1 = acc[t][u][1];
            float v2 = acc[t][u][2], v3 = acc[t][u][3];
            if (!isY) {
                float2 bb = *(const float2*)(bias + col);
                v0 += bb.x; v1 += bb.y; v2 += bb.x; v3 += bb.y;
            }
            if (m0 < NN)     *(__half2*)(C + (size_t)m0 * 256 + col)       = __floats2half2_rn(v0, v1);
            if (m0 + 8 < NN) *(__half2*)(C + (size_t)(m0 + 8) * 256 + col) = __floats2half2_rn(v2, v3);
        }
    }
}

// ------ aggregation: out = relu(gather_sum(Yh) + Zh) — R10 body, 64-thr blocks
// Small blocks (2 warps) cut the block-retirement tail from max-of-8 node
// degrees to max-of-2 (degrees ~Poisson(16)).
// Ahout != nullptr: fp16 out (layers 1..5). F32out != nullptr: fp32 out (last
// layer; final activations exceed fp16 range — see R11 post-mortem).
__global__ void aggregate_relu_kernel(const __half* __restrict__ Yh, const __half* __restrict__ Zh,
                                      const int* __restrict__ rowptr, const int* __restrict__ csr,
                                      __half* __restrict__ Ahout, float* __restrict__ F32out,
                                      int n) {
    int warp = (blockIdx.x * blockDim.x + threadIdx.x) >> 5;
    int lane = threadIdx.x & 31;
    if (warp >= n) return;
    int beg = rowptr[warp], end = rowptr[warp + 1];
    size_t off = (size_t)warp * HH + lane * 8;

    float4 acc0, acc1;
    {
        uint4 q = *(const uint4*)(Zh + off);
        float2 f0 = __half22float2(*(__half2*)&q.x);
        float2 f1 = __half22float2(*(__half2*)&q.y);
        float2 f2 = __half22float2(*(__half2*)&q.z);
        float2 f3 = __half22float2(*(__half2*)&q.w);
        acc0 = make_float4(f0.x, f0.y, f1.x, f1.y);
        acc1 = make_float4(f2.x, f2.y, f3.x, f3.y);
    }
    for (int e = beg; e < end; e++) {
        int s0 = csr[e];
        uint4 q = *(const uint4*)(Yh + (size_t)s0 * HH + lane * 8);   // 8 halves
        float2 f0 = __half22float2(*(__half2*)&q.x);
        float2 f1 = __half22float2(*(__half2*)&q.y);
        float2 f2 = __half22float2(*(__half2*)&q.z);
        float2 f3 = __half22float2(*(__half2*)&q.w);
        acc0.x += f0.x; acc0.y += f0.y; acc0.z += f1.x; acc0.w += f1.y;
        acc1.x += f2.x; acc1.y += f2.y; acc1.z += f3.x; acc1.w += f3.y;
    }
    acc0.x = fmaxf(acc0.x, 0.f); acc0.y = fmaxf(acc0.y, 0.f);
    acc0.z = fmaxf(acc0.z, 0.f); acc0.w = fmaxf(acc0.w, 0.f);
    acc1.x = fmaxf(acc1.x, 0.f); acc1.y = fmaxf(acc1.y, 0.f);
    acc1.z = fmaxf(acc1.z, 0.f); acc1.w = fmaxf(acc1.w, 0.f);

    if (F32out) {
        *(float4*)(F32out + off)     = acc0;
        *(float4*)(F32out + off + 4) = acc1;
    }
    if (Ahout) {
        uint4 o;
        *(__half2*)&o.x = __floats2half2_rn(acc0.x, acc0.y);
        *(__half2*)&o.y = __floats2half2_rn(acc0.z, acc0.w);
        *(__half2*)&o.z = __floats2half2_rn(acc1.x, acc1.y);
        *(__half2*)&o.w = __floats2half2_rn(acc1.z, acc1.w);
        *(uint4*)(Ahout + off) = o;
    }
}

// ------- fused mean-pool + head: block g -> out[g][0..23] --------------------
__device__ __forceinline__ int lower_bound_dev(const int* a, int n, int key) {
    int lo = 0, hi = n;
    while (lo < hi) {
        int mid = (lo + hi) >> 1;
        if (a[mid] < key) lo = mid + 1; else hi = mid;
    }
    return lo;
}

__global__ void pool_head_kernel(const float* __restrict__ H, const int* __restrict__ batch,
                                 const float* __restrict__ w_out, const float* __restrict__ b_out,
                                 float* __restrict__ out, int n) {
    int g = blockIdx.x;
    int j = threadIdx.x;  // 256
    __shared__ int s_lo, s_hi;
    __shared__ float s_pool[HH];
    if (j == 0) {
        s_lo = lower_bound_dev(batch, n, g);
        s_hi = lower_bound_dev(batch, n, g + 1);
    }
    __syncthreads();
    int lo = s_lo, hi = s_hi;
    float acc = 0.f;
    for (int nd = lo; nd < hi; nd++) acc += H[(size_t)nd * HH + j];
    int cnt = hi - lo;
    s_pool[j] = acc / (float)max(cnt, 1);
    __syncthreads();
    if (j < OUTD) {
        float o = b_out[j];
        #pragma unroll 8
        for (int k = 0; k < HH; k++)
            o += s_pool[k] * w_out[k * OUTD + j];
        out[g * OUTD + j] = o;
    }
}

// ---------------- launch -----------------------------------------------------
extern "C" void kernel_launch(void* const* d_in, const int* in_sizes, int n_in,
                              void* d_out, int out_size) {
    const float* x       = (const float*)d_in[0];
    const int*   ei      = (const int*)d_in[1];
    const int*   batch   = (const int*)d_in[2];
    const float* w_rel1  = (const float*)d_in[3];
    const float* w_root1 = (const float*)d_in[4];
    const float* b1      = (const float*)d_in[5];
    const float* w_rel   = (const float*)d_in[6];   // 6 x 256 x 256
    const float* w_root  = (const float*)d_in[7];
    const float* b       = (const float*)d_in[8];   // 6 x 256
    const float* w_out   = (const float*)d_in[9];
    const float* b_out   = (const float*)d_in[10];
    float* out = (float*)d_out;

    const int* src = ei;        // edge_index[0]
    const int* dst = ei + EE;   // edge_index[1]

    float *hf, *agg3;
    __half *yh, *zh, *Ah, *Bh;
    int *deg, *rowptr, *cursor, *csr, *bsums;
    cudaGetSymbolAddress((void**)&hf, g_hf);
    cudaGetSymbolAddress((void**)&yh, g_yh);
    cudaGetSymbolAddress((void**)&zh, g_zh);
    cudaGetSymbolAddress((void**)&agg3, g_agg3);
    cudaGetSymbolAddress((void**)&deg, g_deg);
    cudaGetSymbolAddress((void**)&rowptr, g_rowptr);
    cudaGetSymbolAddress((void**)&cursor, g_cursor);
    cudaGetSymbolAddress((void**)&csr, g_csr);
    cudaGetSymbolAddress((void**)&bsums, g_bsums);
    cudaGetSymbolAddress((void**)&Ah, g_Ah);
    cudaGetSymbolAddress((void**)&Bh, g_Bh);

    cudaFuncSetAttribute(gemm_tc_kernel, cudaFuncAttributeMaxDynamicSharedMemorySize, GEMM_SMEM_TOTAL);

    // ---- build CSR (once per launch) ----
    zero2_kernel<<<(NN + 255) / 256, 256>>>(deg, cursor, NN);
    count_deg_kernel<<<(EE + 255) / 256, 256>>>(dst, deg, EE);
    scan_pass1<<<SCAN_BLOCKS, 256>>>(deg, bsums, NN);
    scan_pass3<<<SCAN_BLOCKS, 256>>>(deg, bsums, rowptr, NN, SCAN_BLOCKS);
    fill_csr_kernel<<<(EE + 255) / 256, 256>>>(src, dst, rowptr, cursor, csr, EE);

    // ---- weight prep (fp16, K-major) ----
    prep_weights_kernel<<<(6 * 512 * 256 + 255) / 256, 256>>>(w_rel, w_root, Bh);

    // ---- layer 1 (3 -> 256), fp32 -> Ah fp16 directly ----
    aggx_kernel<<<(NN + 255) / 256, 256>>>(x, rowptr, csr, agg3, NN);
    layer1_kernel<<<NN, 256>>>(x, agg3, w_rel1, w_root1, b1, Ah);

    // ---- layers 2..7 (256 -> 256), tensor cores via mma.sync fp16 ----
    dim3 ggrid(NPAD / 128, 4);
    for (int i = 0; i < 6; i++) {
        gemm_tc_kernel<<<ggrid, 256, GEMM_SMEM_TOTAL>>>(Ah, Bh + (size_t)i * 512 * 256,
                                                        b + i * HH, yh, zh);
        bool last = (i == 5);
        // 64-thread blocks: 2 nodes/block -> small block-retirement tail
        aggregate_relu_kernel<<<(NN * 32 + 63) / 64, 64>>>(
            yh, zh, rowptr, csr,
            last ? (__half*)nullptr : Ah,
            last ? hf : (float*)nullptr, NN);
    }

    // ---- fused pool + head (reads fp32 hf — final layer exceeds fp16 range) --
    pool_head_kernel<<<GG, 256>>>(hf, batch, w_out, b_out, out, NN);
}

// round 17
// speedup vs baseline: 1.1352x; 1.0695x over previous
#include <cuda_runtime.h>
#include <cuda_bf16.h>
#include <cuda_fp16.h>
#include <cstdint>

// Problem constants (fixed by the dataset)
#define NN   50000
#define NPAD 50048        // 391 * 128
#define EE   800000
#define FIN  3
#define HH   256
#define GG   64
#define OUTD 24

// ---------------- scratch (device globals; no allocation allowed) -----------
__device__ float g_hf[NN * HH];           // final-layer fp32 activations (range > fp16 max!)
__device__ float g_agg3[NN * FIN];
__device__ int   g_deg[NN + 1];
__device__ int   g_rowptr[NN + 1];
__device__ int   g_cursor[NN + 1];
__device__ int   g_csr[EE];
__device__ int   g_bsums[256];
// A' buffers: row = [agg/32 (256 halves) | h (256 halves)], double-buffered.
// Pad rows (NN..NPAD) are never written -> stay zero (static init).
__device__ __half g_Ap0[(size_t)NPAD * 512];
__device__ __half g_Ap1[(size_t)NPAD * 512];
// B' per layer: [n(256)][k(512)] fp16, K-major; k<256 -> 32*w_rel, k>=256 -> w_root
__device__ __half g_Bp[(size_t)6 * 256 * 512];

// ---------------- PTX helpers (family-safe only: mma.sync / ldmatrix / cp.async)
__device__ __forceinline__ uint32_t smem_u32(const void* p) {
    uint32_t a;
    asm("{ .reg .u64 t; cvta.to.shared.u64 t, %1; cvt.u32.u64 %0, t; }" : "=r"(a) : "l"(p));
    return a;
}
__device__ __forceinline__ void cp16(uint32_t saddr, const void* gptr) {
    asm volatile("cp.async.cg.shared.global [%0], [%1], 16;" :: "r"(saddr), "l"(gptr) : "memory");
}
__device__ __forceinline__ void cp_commit() {
    asm volatile("cp.async.commit_group;" ::: "memory");
}
__device__ __forceinline__ void cp_wait2() {
    asm volatile("cp.async.wait_group 2;" ::: "memory");
}
__device__ __forceinline__ void cp_wait1() {
    asm volatile("cp.async.wait_group 1;" ::: "memory");
}
__device__ __forceinline__ void cp_wait0() {
    asm volatile("cp.async.wait_group 0;" ::: "memory");
}
__device__ __forceinline__ void ldmx4(uint32_t* r, uint32_t addr) {
    asm volatile("ldmatrix.sync.aligned.m8n8.x4.shared.b16 {%0,%1,%2,%3}, [%4];"
                 : "=r"(r[0]), "=r"(r[1]), "=r"(r[2]), "=r"(r[3]) : "r"(addr));
}
__device__ __forceinline__ void mma16816(float* c, const uint32_t* a, uint32_t b0, uint32_t b1) {
    asm volatile(
        "mma.sync.aligned.m16n8k16.row.col.f32.f16.f16.f32 "
        "{%0,%1,%2,%3}, {%4,%5,%6,%7}, {%8,%9}, {%0,%1,%2,%3};"
        : "+f"(c[0]), "+f"(c[1]), "+f"(c[2]), "+f"(c[3])
        : "r"(a[0]), "r"(a[1]), "r"(a[2]), "r"(a[3]), "r"(b0), "r"(b1));
}
// 128B-atom XOR swizzle (bank-conflict-free STS/ldmatrix)
__device__ __forceinline__ uint32_t SWZ(uint32_t x) { return x ^ (((x) >> 3) & 0x70); }

// ---------------- CSR construction ------------------------------------------
__global__ void zero2_kernel(int* a, int* b, int n) {
    int i = blockIdx.x * blockDim.x + threadIdx.x;
    if (i < n) { a[i] = 0; b[i] = 0; }
}

__global__ void count_deg_kernel(const int* __restrict__ dst, int* __restrict__ deg, int e) {
    int i = blockIdx.x * blockDim.x + threadIdx.x;
    if (i < e) atomicAdd(&deg[dst[i]], 1);
}

#define SCAN_BLOCKS ((NN + 255) / 256)   // 196

__global__ void scan_pass1(const int* __restrict__ deg, int* __restrict__ bsums, int n) {
    int i = blockIdx.x * 256 + threadIdx.x;
    int v = (i < n) ? deg[i] : 0;
    #pragma unroll
    for (int o = 16; o > 0; o >>= 1) v += __shfl_down_sync(0xFFFFFFFF, v, o);
    __shared__ int ws[8];
    int wid = threadIdx.x >> 5, lane = threadIdx.x & 31;
    if (lane == 0) ws[wid] = v;
    __syncthreads();
    if (threadIdx.x == 0) {
        int s = 0;
        #pragma unroll
        for (int w = 0; w < 8; w++) s += ws[w];
        bsums[blockIdx.x] = s;
    }
}

// pass3 also computes its own exclusive prefix of bsums (196 elems, cheap)
__global__ void scan_pass3(const int* __restrict__ deg, const int* __restrict__ bsums,
                           int* __restrict__ rowptr, int n, int nb) {
    __shared__ int sh[256];
    __shared__ int s_base;
    int i = blockIdx.x * 256 + threadIdx.x;
    int tid = threadIdx.x;

    if (tid < 32) {
        int s = 0;
        for (int j = tid; j < blockIdx.x; j += 32) s += bsums[j];
        #pragma unroll
        for (int o = 16; o > 0; o >>= 1) s += __shfl_down_sync(0xFFFFFFFF, s, o);
        if (tid == 0) s_base = s;
    }

    int v = (i < n) ? deg[i] : 0;
    sh[tid] = v;
    __syncthreads();
    #pragma unroll
    for (int off = 1; off < 256; off <<= 1) {
        int t = (tid >= off) ? sh[tid - off] : 0;
        __syncthreads();
        sh[tid] += t;
        __syncthreads();
    }
    int incl = sh[tid];
    int base = s_base;
    if (i < n)  rowptr[i] = base + incl - v;
    if (i == n - 1) rowptr[n] = base + incl;
}

__global__ void fill_csr_kernel(const int* __restrict__ src, const int* __restrict__ dst,
                                const int* __restrict__ rowptr, int* __restrict__ cursor,
                                int* __restrict__ csr, int e) {
    int i = blockIdx.x * blockDim.x + threadIdx.x;
    if (i < e) {
        int d = dst[i];
        int pos = atomicAdd(&cursor[d], 1);
        csr[rowptr[d] + pos] = src[i];
    }
}

// ---------------- layer 1 (F_IN=3 -> H), writes h into Ap0 h-half ------------
__global__ void aggx_kernel(const float* __restrict__ x,
                            const int* __restrict__ rowptr, const int* __restrict__ csr,
                            float* __restrict__ agg3, int n) {
    int i = blockIdx.x * blockDim.x + threadIdx.x;
    if (i >= n) return;
    float a0 = 0.f, a1 = 0.f, a2 = 0.f;
    int beg = rowptr[i], end = rowptr[i + 1];
    for (int e = beg; e < end; e++) {
        int s = csr[e];
        a0 += x[s * 3 + 0];
        a1 += x[s * 3 + 1];
        a2 += x[s * 3 + 2];
    }
    agg3[i * 3 + 0] = a0;
    agg3[i * 3 + 1] = a1;
    agg3[i * 3 + 2] = a2;
}

__global__ void layer1_kernel(const float* __restrict__ x, const float* __restrict__ agg3,
                              const float* __restrict__ wr, const float* __restrict__ wro,
                              const float* __restrict__ b1, __half* __restrict__ Ap) {
    int n = blockIdx.x;
    int j = threadIdx.x;  // 256
    __shared__ float sx[3], sa[3];
    if (j < 3) { sx[j] = x[n * 3 + j]; sa[j] = agg3[n * 3 + j]; }
    __syncthreads();
    float v = b1[j];
    #pragma unroll
    for (int f = 0; f < 3; f++)
        v += sa[f] * wr[f * HH + j] + sx[f] * wro[f * HH + j];
    v = fmaxf(v, 0.f);
    Ap[(size_t)n * 512 + 256 + j] = __float2half_rn(v);
}

// ------ weight prep: B'[n][k] = (k<256 ? 32*w_rel[k][n] : w_root[k-256][n]) --
__global__ void prep_weights_kernel(const float* __restrict__ w_rel, const float* __restrict__ w_root,
                                    __half* __restrict__ Bp) {
    int idx = blockIdx.x * blockDim.x + threadIdx.x;
    if (idx >= 6 * 256 * 512) return;
    int k = idx & 511;
    int n = (idx >> 9) & 255;
    int L = idx >> 17;     // 256*512 = 2^17
    float w = (k < 256) ? 32.f * w_rel[(size_t)L * 65536 + k * 256 + n]
                        : w_root[(size_t)L * 65536 + (k - 256) * 256 + n];
    Bp[(size_t)L * 131072 + (size_t)n * 512 + k] = __float2half_rn(w);
}

// ------ aggregation (pre-GEMM): agg_i = (sum_j h_j)/32, fp16, into agg-half --
// 64-thread blocks (2 warps): small block-retirement tail.
__global__ void aggregate_h_kernel(const int* __restrict__ rowptr, const int* __restrict__ csr,
                                   __half* __restrict__ Ap, int n) {
    int warp = (blockIdx.x * blockDim.x + threadIdx.x) >> 5;
    int lane = threadIdx.x & 31;
    if (warp >= n) return;
    int beg = rowptr[warp], end = rowptr[warp + 1];

    float a0 = 0.f, a1 = 0.f, a2 = 0.f, a3 = 0.f, a4 = 0.f, a5 = 0.f, a6 = 0.f, a7 = 0.f;
    const __half* hbase = Ap + 256 + lane * 8;
    for (int e = beg; e < end; e++) {
        int s0 = csr[e];
        uint4 q = *(const uint4*)(hbase + (size_t)s0 * 512);   // 8 halves of h
        float2 f0 = __half22float2(*(__half2*)&q.x);
        float2 f1 = __half22float2(*(__half2*)&q.y);
        float2 f2 = __half22float2(*(__half2*)&q.z);
        float2 f3 = __half22float2(*(__half2*)&q.w);
        a0 += f0.x; a1 += f0.y; a2 += f1.x; a3 += f1.y;
        a4 += f2.x; a5 += f2.y; a6 += f3.x; a7 += f3.y;
    }
    const float s = 1.f / 32.f;   // folded back via 32*w_rel (exact power of 2)
    uint4 o;
    *(__half2*)&o.x = __floats2half2_rn(a0 * s, a1 * s);
    *(__half2*)&o.y = __floats2half2_rn(a2 * s, a3 * s);
    *(__half2*)&o.z = __floats2half2_rn(a4 * s, a5 * s);
    *(__half2*)&o.w = __floats2half2_rn(a6 * s, a7 * s);
    *(uint4*)(Ap + (size_t)warp * 512 + lane * 8) = o;
}

// ---------------- mma.sync GEMM ----------------------------------------------
// h'[128,128] per CTA = relu(A'[M,512] x B'^T + bias); fp16 in, fp32 acc.
// grid (391, 2): nb selects output cols [nb*128, nb*128+128).
// 8 warps: wm = wid>>1 (4 x 32 rows), wn = wid&1 (2 x 64 cols).
// K = 512 = 8 chunks of 64; SMEM: 3-stage ring x 32KB = 96KB.
#define GEMM_STAGE      32768
#define GEMM_SMEM_TOTAL (3 * GEMM_STAGE)
#define K_CHUNKS 8

__device__ __forceinline__ void load_chunk_cp(uint32_t sdst, int c, int bm, int nb,
                                              const __half* __restrict__ Ap,
                                              const __half* __restrict__ Bp) {
    int tid = threadIdx.x;
    #pragma unroll
    for (int i = 0; i < 4; i++) {                  // A': 128 rows x 128B
        int v = tid + i * 256;
        int r = v >> 3, kc = v & 7;
        const void* g = Ap + (size_t)(bm + r) * 512 + c * 64 + kc * 8;
        cp16(sdst + SWZ(r * 128 + kc * 16), g);
    }
    uint32_t bdst = sdst + 16384;
    #pragma unroll
    for (int i = 0; i < 4; i++) {                  // B': 128 n-rows x 128B
        int v = tid + i * 256;
        int r = v >> 3, kc = v & 7;
        const void* g = Bp + (size_t)(nb * 128 + r) * 512 + c * 64 + kc * 8;
        cp16(bdst + SWZ(r * 128 + kc * 16), g);
    }
}

__global__ __launch_bounds__(256, 2)
void gemm_tc_kernel(const __half* __restrict__ Ap, const __half* __restrict__ Bp,
                    const float* __restrict__ bias,
                    __half* __restrict__ ApNext, float* __restrict__ hfOut) {
    extern __shared__ char smem[];
    uint32_t sb = smem_u32(smem);
    int tid = threadIdx.x, wid = tid >> 5, lane = tid & 31;
    int bm = blockIdx.x * 128;
    int nb = blockIdx.y;
    int wm = wid >> 1, wn = wid & 1;

    float acc[2][8][4];
    #pragma unroll
    for (int t = 0; t < 2; t++)
        #pragma unroll
        for (int u = 0; u < 8; u++)
            #pragma unroll
            for (int e = 0; e < 4; e++) acc[t][u][e] = 0.f;

    // 3-stage prologue
    load_chunk_cp(sb + 0 * GEMM_STAGE, 0, bm, nb, Ap, Bp);
    cp_commit();
    load_chunk_cp(sb + 1 * GEMM_STAGE, 1, bm, nb, Ap, Bp);
    cp_commit();

    #pragma unroll
    for (int ch = 0; ch < K_CHUNKS; ch++) {
        if (ch + 2 < K_CHUNKS) {
            load_chunk_cp(sb + ((ch + 2) % 3) * GEMM_STAGE, ch + 2, bm, nb, Ap, Bp);
            cp_commit();
        }
        if (ch < K_CHUNKS - 2)      cp_wait2();
        else if (ch == K_CHUNKS - 2) cp_wait1();
        else                         cp_wait0();
        __syncthreads();

        uint32_t As = sb + (ch % 3) * GEMM_STAGE;
        uint32_t Bs = As + 16384;
        #pragma unroll
        for (int s = 0; s < 4; s++) {
            uint32_t a[2][4], bfrag[4][4];
            #pragma unroll
            for (int t = 0; t < 2; t++) {
                int m_local = wm * 32 + t * 16 + ((lane >> 3) & 1) * 8 + (lane & 7);
                int kseg = s * 2 + (lane >> 4);
                ldmx4(a[t], As + SWZ(m_local * 128 + kseg * 16));
            }
            #pragma unroll
            for (int j = 0; j < 4; j++) {
                int n_local = wn * 64 + (2 * j + (lane >> 4)) * 8 + (lane & 7);
                int kseg = s * 2 + ((lane >> 3) & 1);
                ldmx4(bfrag[j], Bs + SWZ(n_local * 128 + kseg * 16));
            }
            #pragma unroll
            for (int t = 0; t < 2; t++)
                #pragma unroll
                for (int u = 0; u < 8; u++)
                    mma16816(acc[t][u], a[t], bfrag[u >> 1][(u & 1) * 2],
                             bfrag[u >> 1][(u & 1) * 2 + 1]);
        }
        __syncthreads();
    }

    // epilogue: h' = relu(acc + bias); fp16 into ApNext h-half, or fp32 hf (last)
    int colbase = nb * 128 + wn * 64;
    #pragma unroll
    for (int t = 0; t < 2; t++) {
        int m0 = bm + wm * 32 + t * 16 + (lane >> 2);
        #pragma unroll
        for (int u = 0; u < 8; u++) {
            int col = colbase + u * 8 + (lane & 3) * 2;
            float2 bb = *(const float2*)(bias + col);
            float v0 = fmaxf(acc[t][u][0] + bb.x, 0.f);
            float v1 = fmaxf(acc[t][u][1] + bb.y, 0.f);
            float v2 = fmaxf(acc[t][u][2] + bb.x, 0.f);
            float v3 = fmaxf(acc[t][u][3] + bb.y, 0.f);
            if (hfOut) {
                if (m0 < NN)     { float2 w = make_float2(v0, v1); *(float2*)(hfOut + (size_t)m0 * 256 + col) = w; }
                if (m0 + 8 < NN) { float2 w = make_float2(v2, v3); *(float2*)(hfOut + (size_t)(m0 + 8) * 256 + col) = w; }
            } else {
                if (m0 < NN)     *(__half2*)(ApNext + (size_t)m0 * 512 + 256 + col)       = __floats2half2_rn(v0, v1);
                if (m0 + 8 < NN) *(__half2*)(ApNext + (size_t)(m0 + 8) * 512 + 256 + col) = __floats2half2_rn(v2, v3);
            }
        }
    }
}

// ------- fused mean-pool + head: block g -> out[g][0..23] --------------------
__device__ __forceinline__ int lower_bound_dev(const int* a, int n, int key) {
    int lo = 0, hi = n;
    while (lo < hi) {
        int mid = (lo + hi) >> 1;
        if (a[mid] < key) lo = mid + 1; else hi = mid;
    }
    return lo;
}

__global__ void pool_head_kernel(const float* __restrict__ H, const int* __restrict__ batch,
                                 const float* __restrict__ w_out, const float* __restrict__ b_out,
                                 float* __restrict__ out, int n) {
    int g = blockIdx.x;
    int j = threadIdx.x;  // 256
    __shared__ int s_lo, s_hi;
    __shared__ float s_pool[HH];
    if (j == 0) {
        s_lo = lower_bound_dev(batch, n, g);
        s_hi = lower_bound_dev(batch, n, g + 1);
    }
    __syncthreads();
    int lo = s_lo, hi = s_hi;
    float acc = 0.f;
    for (int nd = lo; nd < hi; nd++) acc += H[(size_t)nd * HH + j];
    int cnt = hi - lo;
    s_pool[j] = acc / (float)max(cnt, 1);
    __syncthreads();
    if (j < OUTD) {
        float o = b_out[j];
        #pragma unroll 8
        for (int k = 0; k < HH; k++)
            o += s_pool[k] * w_out[k * OUTD + j];
        out[g * OUTD + j] = o;
    }
}

// ---------------- launch -----------------------------------------------------
extern "C" void kernel_launch(void* const* d_in, const int* in_sizes, int n_in,
                              void* d_out, int out_size) {
    const float* x       = (const float*)d_in[0];
    const int*   ei      = (const int*)d_in[1];
    const int*   batch   = (const int*)d_in[2];
    const float* w_rel1  = (const float*)d_in[3];
    const float* w_root1 = (const float*)d_in[4];
    const float* b1      = (const float*)d_in[5];
    const float* w_rel   = (const float*)d_in[6];   // 6 x 256 x 256
    const float* w_root  = (const float*)d_in[7];
    const float* b       = (const float*)d_in[8];   // 6 x 256
    const float* w_out   = (const float*)d_in[9];
    const float* b_out   = (const float*)d_in[10];
    float* out = (float*)d_out;

    const int* src = ei;        // edge_index[0]
    const int* dst = ei + EE;   // edge_index[1]

    float *hf, *agg3;
    __half *Ap0, *Ap1, *Bp;
    int *deg, *rowptr, *cursor, *csr, *bsums;
    cudaGetSymbolAddress((void**)&hf, g_hf);
    cudaGetSymbolAddress((void**)&agg3, g_agg3);
    cudaGetSymbolAddress((void**)&deg, g_deg);
    cudaGetSymbolAddress((void**)&rowptr, g_rowptr);
    cudaGetSymbolAddress((void**)&cursor, g_cursor);
    cudaGetSymbolAddress((void**)&csr, g_csr);
    cudaGetSymbolAddress((void**)&bsums, g_bsums);
    cudaGetSymbolAddress((void**)&Ap0, g_Ap0);
    cudaGetSymbolAddress((void**)&Ap1, g_Ap1);
    cudaGetSymbolAddress((void**)&Bp, g_Bp);

    cudaFuncSetAttribute(gemm_tc_kernel, cudaFuncAttributeMaxDynamicSharedMemorySize, GEMM_SMEM_TOTAL);

    // ---- build CSR (once per launch) ----
    zero2_kernel<<<(NN + 255) / 256, 256>>>(deg, cursor, NN);
    count_deg_kernel<<<(EE + 255) / 256, 256>>>(dst, deg, EE);
    scan_pass1<<<SCAN_BLOCKS, 256>>>(deg, bsums, NN);
    scan_pass3<<<SCAN_BLOCKS, 256>>>(deg, bsums, rowptr, NN, SCAN_BLOCKS);
    fill_csr_kernel<<<(EE + 255) / 256, 256>>>(src, dst, rowptr, cursor, csr, EE);

    // ---- weight prep (fp16 B' = [32*w_rel ; w_root], K-major) ----
    prep_weights_kernel<<<(6 * 256 * 512 + 255) / 256, 256>>>(w_rel, w_root, Bp);

    // ---- layer 1 (3 -> 256), fp32 -> h-half of Ap0 ----
    aggx_kernel<<<(NN + 255) / 256, 256>>>(x, rowptr, csr, agg3, NN);
    layer1_kernel<<<NN, 256>>>(x, agg3, w_rel1, w_root1, b1, Ap0);

    // ---- layers 2..7: aggregate h -> agg-half, then K=512 GEMM -> next h ----
    dim3 ggrid(NPAD / 128, 2);
    __half* cur = Ap0;
    __half* nxt = Ap1;
    for (int i = 0; i < 6; i++) {
        aggregate_h_kernel<<<(NN * 32 + 63) / 64, 64>>>(rowptr, csr, cur, NN);
        bool last = (i == 5);
        gemm_tc_kernel<<<ggrid, 256, GEMM_SMEM_TOTAL>>>(
            cur, Bp + (size_t)i * 131072, b + i * HH,
            last ? (__half*)nullptr : nxt,
            last ? hf : (float*)nullptr);
        __half* t = cur; cur = nxt; nxt = t;
    }

    // ---- fused pool + head (reads fp32 hf — final layer exceeds fp16 range) --
    pool_head_kernel<<<GG, 256>>>(hf, batch, w_out, b_out, out, NN);
}